// round 2
// baseline (speedup 1.0000x reference)
#include <cuda_runtime.h>

// Problem constants: B=8, H=8, S=1024, D=64
#define BH      64
#define SEQ     1024
#define HD      64
#define NROWS   (BH * SEQ)          // 65536 total (b,h,s) rows

// Scratch for projected q/k/v (allocation-free rule: __device__ globals)
__device__ float g_q[NROWS * HD];
__device__ float g_k[NROWS * HD];
__device__ float g_v[NROWS * HD];

// ---------------------------------------------------------------------------
// Projection: Y[r][e] = relu( sum_d X[r][d] * W[e][d] + bias[e] )
// One block = 64 rows x 64 outputs. 256 threads, 4x4 micro-tile per thread.
// ---------------------------------------------------------------------------
__global__ __launch_bounds__(256) void proj_kernel(
    const float* __restrict__ X, const float* __restrict__ W,
    const float* __restrict__ bias, int which)
{
    float* __restrict__ Y = (which == 0) ? g_q : (which == 1) ? g_k : g_v;

    __shared__ __align__(16) float Xs[64 * 64];
    __shared__ __align__(16) float Ws[64 * 64];

    const int tid = threadIdx.x;
    const size_t rowBase = (size_t)blockIdx.x * 64;

    // Stage X tile and full W into smem (float4, coalesced)
    {
        const float4* xs = (const float4*)(X + rowBase * HD);
        const float4* ws = (const float4*)W;
        float4* Xd = (float4*)Xs;
        float4* Wd = (float4*)Ws;
#pragma unroll
        for (int i = 0; i < 4; i++) {
            Xd[tid + i * 256] = xs[tid + i * 256];
            Wd[tid + i * 256] = ws[tid + i * 256];
        }
    }
    __syncthreads();

    const int tr = tid >> 4;    // 0..15 -> rows tr*4..tr*4+3
    const int tc = tid & 15;    // 0..15 -> cols tc*4..tc*4+3

    float acc[4][4] = {};
#pragma unroll
    for (int k = 0; k < 64; k += 4) {
        float4 a[4], b[4];
#pragma unroll
        for (int i = 0; i < 4; i++) a[i] = *(const float4*)&Xs[(tr * 4 + i) * 64 + k];
#pragma unroll
        for (int j = 0; j < 4; j++) b[j] = *(const float4*)&Ws[(tc * 4 + j) * 64 + k];
#pragma unroll
        for (int i = 0; i < 4; i++)
#pragma unroll
            for (int j = 0; j < 4; j++)
                acc[i][j] += a[i].x * b[j].x + a[i].y * b[j].y +
                             a[i].z * b[j].z + a[i].w * b[j].w;
    }

    const float4 bv = *(const float4*)&bias[tc * 4];
#pragma unroll
    for (int i = 0; i < 4; i++) {
        float4 o;
        o.x = fmaxf(acc[i][0] + bv.x, 0.0f);
        o.y = fmaxf(acc[i][1] + bv.y, 0.0f);
        o.z = fmaxf(acc[i][2] + bv.z, 0.0f);
        o.w = fmaxf(acc[i][3] + bv.w, 0.0f);
        *(float4*)&Y[(rowBase + tr * 4 + i) * HD + tc * 4] = o;
    }
}

// ---------------------------------------------------------------------------
// Attention: flash-style online softmax per (bh, 64-query tile).
//   score = softmax(q k^T / 8); a = score v
// Epilogue applies the reference's transpose(0,1,3,2)+reshape mangle and adds
// the raw-queries residual:  out[bh][lin] = a[lin & 1023][lin >> 10] + q_in[bh][lin]
// Static smem = exactly 48KB: Qs | KP (K, later reused for P) | Vs.
// Epilogue buffer As (64x65, conflict-free transpose) overlaps Qs+KP head.
// ---------------------------------------------------------------------------
__global__ __launch_bounds__(256) void attn_kernel(
    const float* __restrict__ queries_in, float* __restrict__ out)
{
    __shared__ __align__(16) float smem[12288];   // 48 KB
    float* Qs = smem;            // 64x64
    float* KP = smem + 4096;     // 64x64 : K tile, then P tile
    float* Vs = smem + 8192;     // 64x64
    float* As = smem;            // 64x65 = 4160 floats (overlaps Qs + KP[0:64])

    const int tid = threadIdx.x;
    const int tr = tid >> 4;
    const int tc = tid & 15;
    const int bh = blockIdx.y;
    const int qbase = blockIdx.x * 64;
    const size_t base = (size_t)bh * (SEQ * HD);

    // Load Q tile
    {
        const float4* src = (const float4*)(g_q + base + (size_t)qbase * HD);
        float4* dst = (float4*)Qs;
#pragma unroll
        for (int i = 0; i < 4; i++) dst[tid + i * 256] = src[tid + i * 256];
    }

    float m[4], l[4], o[4][4];
#pragma unroll
    for (int i = 0; i < 4; i++) {
        m[i] = -1e30f; l[i] = 0.0f;
#pragma unroll
        for (int j = 0; j < 4; j++) o[i][j] = 0.0f;
    }

    for (int kt = 0; kt < 16; kt++) {
        __syncthreads();   // previous iteration's PV reads of KP/Vs done
        {
            const float4* ks = (const float4*)(g_k + base + (size_t)kt * 64 * HD);
            const float4* vs = (const float4*)(g_v + base + (size_t)kt * 64 * HD);
            float4* kd = (float4*)KP;
            float4* vd = (float4*)Vs;
#pragma unroll
            for (int i = 0; i < 4; i++) {
                kd[tid + i * 256] = ks[tid + i * 256];
                vd[tid + i * 256] = vs[tid + i * 256];
            }
        }
        __syncthreads();

        // s[i][j] = sum_d Q[tr*4+i][d] * K[tc*4+j][d]
        float p[4][4] = {};
#pragma unroll
        for (int k = 0; k < 64; k += 4) {
            float4 a[4], b[4];
#pragma unroll
            for (int i = 0; i < 4; i++) a[i] = *(const float4*)&Qs[(tr * 4 + i) * 64 + k];
#pragma unroll
            for (int j = 0; j < 4; j++) b[j] = *(const float4*)&KP[(tc * 4 + j) * 64 + k];
#pragma unroll
            for (int i = 0; i < 4; i++)
#pragma unroll
                for (int j = 0; j < 4; j++)
                    p[i][j] += a[i].x * b[j].x + a[i].y * b[j].y +
                               a[i].z * b[j].z + a[i].w * b[j].w;
        }
        __syncthreads();   // everyone done reading KP (K) before P overwrites it

#pragma unroll
        for (int i = 0; i < 4; i++)
#pragma unroll
            for (int j = 0; j < 4; j++) p[i][j] *= 0.125f;   // 1/sqrt(64)

        // Online softmax update (rows tr*4+i live on the 16-lane group tc=0..15)
#pragma unroll
        for (int i = 0; i < 4; i++) {
            float tmax = fmaxf(fmaxf(p[i][0], p[i][1]), fmaxf(p[i][2], p[i][3]));
#pragma unroll
            for (int off = 8; off >= 1; off >>= 1)
                tmax = fmaxf(tmax, __shfl_xor_sync(0xffffffffu, tmax, off, 16));
            const float mn = fmaxf(m[i], tmax);
            const float al = __expf(m[i] - mn);
            float tsum = 0.0f;
#pragma unroll
            for (int j = 0; j < 4; j++) { p[i][j] = __expf(p[i][j] - mn); tsum += p[i][j]; }
#pragma unroll
            for (int off = 8; off >= 1; off >>= 1)
                tsum += __shfl_xor_sync(0xffffffffu, tsum, off, 16);
            l[i] = l[i] * al + tsum;
            m[i] = mn;
#pragma unroll
            for (int j = 0; j < 4; j++) o[i][j] *= al;
            *(float4*)&KP[(tr * 4 + i) * 64 + tc * 4] =
                make_float4(p[i][0], p[i][1], p[i][2], p[i][3]);
        }
        __syncthreads();

        // o[i][j] += sum_k P[tr*4+i][k] * V[k][tc*4+j]
#pragma unroll 4
        for (int k = 0; k < 64; k += 4) {
            const float4 v0 = *(const float4*)&Vs[(k + 0) * 64 + tc * 4];
            const float4 v1 = *(const float4*)&Vs[(k + 1) * 64 + tc * 4];
            const float4 v2 = *(const float4*)&Vs[(k + 2) * 64 + tc * 4];
            const float4 v3 = *(const float4*)&Vs[(k + 3) * 64 + tc * 4];
#pragma unroll
            for (int i = 0; i < 4; i++) {
                const float4 pi = *(const float4*)&KP[(tr * 4 + i) * 64 + k];
                o[i][0] += pi.x * v0.x + pi.y * v1.x + pi.z * v2.x + pi.w * v3.x;
                o[i][1] += pi.x * v0.y + pi.y * v1.y + pi.z * v2.y + pi.w * v3.y;
                o[i][2] += pi.x * v0.z + pi.y * v1.z + pi.z * v2.z + pi.w * v3.z;
                o[i][3] += pi.x * v0.w + pi.y * v1.w + pi.z * v2.w + pi.w * v3.w;
            }
        }
    }

    __syncthreads();   // last PV reads of KP done before As overwrites Qs/KP head

    // Normalize and stage into As (stride 65 -> conflict-free transpose reads)
#pragma unroll
    for (int i = 0; i < 4; i++) {
        const float inv = 1.0f / l[i];
#pragma unroll
        for (int j = 0; j < 4; j++)
            As[(tr * 4 + i) * 65 + tc * 4 + j] = o[i][j] * inv;
    }
    __syncthreads();

    // out[bh][lin] = a[s = lin&1023][d = lin>>10] + queries_in[bh][lin],
    // restricted to s in [qbase, qbase+64): lin = d*1024 + qbase + sl
    const float* qin = queries_in + (size_t)bh * (SEQ * HD);
    float* op = out + (size_t)bh * (SEQ * HD);
#pragma unroll
    for (int t = 0; t < 16; t++) {
        const int idx = tid + t * 256;       // 0..4095
        const int d  = idx >> 6;
        const int sl = idx & 63;
        const int lin = d * 1024 + qbase + sl;
        op[lin] = As[sl * 65 + d] + qin[lin];
    }
}

// ---------------------------------------------------------------------------
// Launch: inputs in metadata order:
//  0 queries, 1 keys, 2 values, 3 Wq_w, 4 Wq_b, 5 Wk_w, 6 Wk_b, 7 Wv_w, 8 Wv_b
// ---------------------------------------------------------------------------
extern "C" void kernel_launch(void* const* d_in, const int* in_sizes, int n_in,
                              void* d_out, int out_size)
{
    const float* q  = (const float*)d_in[0];
    const float* k  = (const float*)d_in[1];
    const float* v  = (const float*)d_in[2];
    const float* Wq = (const float*)d_in[3];
    const float* bq = (const float*)d_in[4];
    const float* Wk = (const float*)d_in[5];
    const float* bk = (const float*)d_in[6];
    const float* Wv = (const float*)d_in[7];
    const float* bv = (const float*)d_in[8];
    float* out = (float*)d_out;

    proj_kernel<<<1024, 256>>>(q, Wq, bq, 0);
    proj_kernel<<<1024, 256>>>(k, Wk, bk, 1);
    proj_kernel<<<1024, 256>>>(v, Wv, bv, 2);
    attn_kernel<<<dim3(16, 64), 256>>>(q, out);
}

// round 3
// speedup vs baseline: 1.0012x; 1.0012x over previous
#include <cuda_runtime.h>

// Problem constants: B=8, H=8, S=1024, D=64
#define BH      64
#define SEQ     1024
#define HD      64
#define NROWS   (BH * SEQ)          // 65536 total (b,h,s) rows

// Scratch for projected q/k/v (allocation-free rule: __device__ globals)
__device__ float g_q[NROWS * HD];
__device__ float g_k[NROWS * HD];
__device__ float g_v[NROWS * HD];

// ---------------------------------------------------------------------------
// Projection: Y[r][e] = relu( sum_d X[r][d] * W[e][d] + bias[e] )
// One block = 64 rows x 64 outputs. 256 threads, 4x4 micro-tile per thread.
// ---------------------------------------------------------------------------
__global__ __launch_bounds__(256) void proj_kernel(
    const float* __restrict__ X, const float* __restrict__ W,
    const float* __restrict__ bias, int which)
{
    float* __restrict__ Y = (which == 0) ? g_q : (which == 1) ? g_k : g_v;

    __shared__ __align__(16) float Xs[64 * 64];
    __shared__ __align__(16) float Ws[64 * 64];

    const int tid = threadIdx.x;
    const size_t rowBase = (size_t)blockIdx.x * 64;

    // Stage X tile and full W into smem (float4, coalesced)
    {
        const float4* xs = (const float4*)(X + rowBase * HD);
        const float4* ws = (const float4*)W;
        float4* Xd = (float4*)Xs;
        float4* Wd = (float4*)Ws;
#pragma unroll
        for (int i = 0; i < 4; i++) {
            Xd[tid + i * 256] = xs[tid + i * 256];
            Wd[tid + i * 256] = ws[tid + i * 256];
        }
    }
    __syncthreads();

    const int tr = tid >> 4;    // 0..15 -> rows tr*4..tr*4+3
    const int tc = tid & 15;    // 0..15 -> cols tc*4..tc*4+3

    float acc[4][4] = {};
#pragma unroll
    for (int k = 0; k < 64; k += 4) {
        float4 a[4], b[4];
#pragma unroll
        for (int i = 0; i < 4; i++) a[i] = *(const float4*)&Xs[(tr * 4 + i) * 64 + k];
#pragma unroll
        for (int j = 0; j < 4; j++) b[j] = *(const float4*)&Ws[(tc * 4 + j) * 64 + k];
#pragma unroll
        for (int i = 0; i < 4; i++)
#pragma unroll
            for (int j = 0; j < 4; j++)
                acc[i][j] += a[i].x * b[j].x + a[i].y * b[j].y +
                             a[i].z * b[j].z + a[i].w * b[j].w;
    }

    const float4 bv = *(const float4*)&bias[tc * 4];
#pragma unroll
    for (int i = 0; i < 4; i++) {
        float4 o;
        o.x = fmaxf(acc[i][0] + bv.x, 0.0f);
        o.y = fmaxf(acc[i][1] + bv.y, 0.0f);
        o.z = fmaxf(acc[i][2] + bv.z, 0.0f);
        o.w = fmaxf(acc[i][3] + bv.w, 0.0f);
        *(float4*)&Y[(rowBase + tr * 4 + i) * HD + tc * 4] = o;
    }
}

// ---------------------------------------------------------------------------
// Attention: flash-style online softmax per (bh, 64-query tile).
//   score = softmax(q k^T / 8); a = score v
// Epilogue applies the reference's transpose(0,1,3,2)+reshape mangle and adds
// the raw-queries residual:  out[bh][lin] = a[lin & 1023][lin >> 10] + q_in[bh][lin]
// Static smem = exactly 48KB: Qs | KP (K, later reused for P) | Vs.
// Epilogue buffer As (64x65, conflict-free transpose) overlaps Qs+KP head.
// ---------------------------------------------------------------------------
__global__ __launch_bounds__(256) void attn_kernel(
    const float* __restrict__ queries_in, float* __restrict__ out)
{
    __shared__ __align__(16) float smem[12288];   // 48 KB
    float* Qs = smem;            // 64x64
    float* KP = smem + 4096;     // 64x64 : K tile, then P tile
    float* Vs = smem + 8192;     // 64x64
    float* As = smem;            // 64x65 = 4160 floats (overlaps Qs + KP[0:64])

    const int tid = threadIdx.x;
    const int tr = tid >> 4;
    const int tc = tid & 15;
    const int bh = blockIdx.y;
    const int qbase = blockIdx.x * 64;
    const size_t base = (size_t)bh * (SEQ * HD);

    // Load Q tile
    {
        const float4* src = (const float4*)(g_q + base + (size_t)qbase * HD);
        float4* dst = (float4*)Qs;
#pragma unroll
        for (int i = 0; i < 4; i++) dst[tid + i * 256] = src[tid + i * 256];
    }

    float m[4], l[4], o[4][4];
#pragma unroll
    for (int i = 0; i < 4; i++) {
        m[i] = -1e30f; l[i] = 0.0f;
#pragma unroll
        for (int j = 0; j < 4; j++) o[i][j] = 0.0f;
    }

    for (int kt = 0; kt < 16; kt++) {
        __syncthreads();   // previous iteration's PV reads of KP/Vs done
        {
            const float4* ks = (const float4*)(g_k + base + (size_t)kt * 64 * HD);
            const float4* vs = (const float4*)(g_v + base + (size_t)kt * 64 * HD);
            float4* kd = (float4*)KP;
            float4* vd = (float4*)Vs;
#pragma unroll
            for (int i = 0; i < 4; i++) {
                kd[tid + i * 256] = ks[tid + i * 256];
                vd[tid + i * 256] = vs[tid + i * 256];
            }
        }
        __syncthreads();

        // s[i][j] = sum_d Q[tr*4+i][d] * K[tc*4+j][d]
        float p[4][4] = {};
#pragma unroll
        for (int k = 0; k < 64; k += 4) {
            float4 a[4], b[4];
#pragma unroll
            for (int i = 0; i < 4; i++) a[i] = *(const float4*)&Qs[(tr * 4 + i) * 64 + k];
#pragma unroll
            for (int j = 0; j < 4; j++) b[j] = *(const float4*)&KP[(tc * 4 + j) * 64 + k];
#pragma unroll
            for (int i = 0; i < 4; i++)
#pragma unroll
                for (int j = 0; j < 4; j++)
                    p[i][j] += a[i].x * b[j].x + a[i].y * b[j].y +
                               a[i].z * b[j].z + a[i].w * b[j].w;
        }
        __syncthreads();   // everyone done reading KP (K) before P overwrites it

#pragma unroll
        for (int i = 0; i < 4; i++)
#pragma unroll
            for (int j = 0; j < 4; j++) p[i][j] *= 0.125f;   // 1/sqrt(64)

        // Online softmax update (rows tr*4+i live on the 16-lane group tc=0..15)
#pragma unroll
        for (int i = 0; i < 4; i++) {
            float tmax = fmaxf(fmaxf(p[i][0], p[i][1]), fmaxf(p[i][2], p[i][3]));
#pragma unroll
            for (int off = 8; off >= 1; off >>= 1)
                tmax = fmaxf(tmax, __shfl_xor_sync(0xffffffffu, tmax, off, 16));
            const float mn = fmaxf(m[i], tmax);
            const float al = __expf(m[i] - mn);
            float tsum = 0.0f;
#pragma unroll
            for (int j = 0; j < 4; j++) { p[i][j] = __expf(p[i][j] - mn); tsum += p[i][j]; }
#pragma unroll
            for (int off = 8; off >= 1; off >>= 1)
                tsum += __shfl_xor_sync(0xffffffffu, tsum, off, 16);
            l[i] = l[i] * al + tsum;
            m[i] = mn;
#pragma unroll
            for (int j = 0; j < 4; j++) o[i][j] *= al;
            *(float4*)&KP[(tr * 4 + i) * 64 + tc * 4] =
                make_float4(p[i][0], p[i][1], p[i][2], p[i][3]);
        }
        __syncthreads();

        // o[i][j] += sum_k P[tr*4+i][k] * V[k][tc*4+j]
#pragma unroll 4
        for (int k = 0; k < 64; k += 4) {
            const float4 v0 = *(const float4*)&Vs[(k + 0) * 64 + tc * 4];
            const float4 v1 = *(const float4*)&Vs[(k + 1) * 64 + tc * 4];
            const float4 v2 = *(const float4*)&Vs[(k + 2) * 64 + tc * 4];
            const float4 v3 = *(const float4*)&Vs[(k + 3) * 64 + tc * 4];
#pragma unroll
            for (int i = 0; i < 4; i++) {
                const float4 pi = *(const float4*)&KP[(tr * 4 + i) * 64 + k];
                o[i][0] += pi.x * v0.x + pi.y * v1.x + pi.z * v2.x + pi.w * v3.x;
                o[i][1] += pi.x * v0.y + pi.y * v1.y + pi.z * v2.y + pi.w * v3.y;
                o[i][2] += pi.x * v0.z + pi.y * v1.z + pi.z * v2.z + pi.w * v3.z;
                o[i][3] += pi.x * v0.w + pi.y * v1.w + pi.z * v2.w + pi.w * v3.w;
            }
        }
    }

    __syncthreads();   // last PV reads of KP done before As overwrites Qs/KP head

    // Normalize and stage into As (stride 65 -> conflict-free transpose reads)
#pragma unroll
    for (int i = 0; i < 4; i++) {
        const float inv = 1.0f / l[i];
#pragma unroll
        for (int j = 0; j < 4; j++)
            As[(tr * 4 + i) * 65 + tc * 4 + j] = o[i][j] * inv;
    }
    __syncthreads();

    // out[bh][lin] = a[s = lin&1023][d = lin>>10] + queries_in[bh][lin],
    // restricted to s in [qbase, qbase+64): lin = d*1024 + qbase + sl
    const float* qin = queries_in + (size_t)bh * (SEQ * HD);
    float* op = out + (size_t)bh * (SEQ * HD);
#pragma unroll
    for (int t = 0; t < 16; t++) {
        const int idx = tid + t * 256;       // 0..4095
        const int d  = idx >> 6;
        const int sl = idx & 63;
        const int lin = d * 1024 + qbase + sl;
        op[lin] = As[sl * 65 + d] + qin[lin];
    }
}

// ---------------------------------------------------------------------------
// Launch: inputs in metadata order:
//  0 queries, 1 keys, 2 values, 3 Wq_w, 4 Wq_b, 5 Wk_w, 6 Wk_b, 7 Wv_w, 8 Wv_b
// ---------------------------------------------------------------------------
extern "C" void kernel_launch(void* const* d_in, const int* in_sizes, int n_in,
                              void* d_out, int out_size)
{
    const float* q  = (const float*)d_in[0];
    const float* k  = (const float*)d_in[1];
    const float* v  = (const float*)d_in[2];
    const float* Wq = (const float*)d_in[3];
    const float* bq = (const float*)d_in[4];
    const float* Wk = (const float*)d_in[5];
    const float* bk = (const float*)d_in[6];
    const float* Wv = (const float*)d_in[7];
    const float* bv = (const float*)d_in[8];
    float* out = (float*)d_out;

    proj_kernel<<<1024, 256>>>(q, Wq, bq, 0);
    proj_kernel<<<1024, 256>>>(k, Wk, bk, 1);
    proj_kernel<<<1024, 256>>>(v, Wv, bv, 2);
    attn_kernel<<<dim3(16, 64), 256>>>(q, out);
}

// round 4
// speedup vs baseline: 2.0424x; 2.0400x over previous
#include <cuda_runtime.h>

// Problem constants: B=8, H=8, S=1024, D=64
#define BH      64
#define SEQ     1024
#define HD      64
#define NROWS   (BH * SEQ)          // 65536 total (b,h,s) rows

// Scratch for projected q/k/v (allocation-free rule: __device__ globals)
// g_q, g_v: [bh][s][d] row-major.  g_k: TRANSPOSED, [bh][d][s].
__device__ float g_q[NROWS * HD];
__device__ float g_k[NROWS * HD];
__device__ float g_v[NROWS * HD];

// ---------------------------------------------------------------------------
// Projection: Y[r][e] = relu( sum_d X[r][d] * W[e][d] + bias[e] )
// One block = 64 rows x 64 outputs. 256 threads, 4x4 micro-tile per thread.
// which==1 (K) stores the result TRANSPOSED per (b,h): g_k[bh][e][s].
// ---------------------------------------------------------------------------
__global__ __launch_bounds__(256) void proj_kernel(
    const float* __restrict__ X, const float* __restrict__ W,
    const float* __restrict__ bias, int which)
{
    float* __restrict__ Y = (which == 0) ? g_q : (which == 1) ? g_k : g_v;

    __shared__ __align__(16) float Xs[64 * 64];
    __shared__ __align__(16) float Ws[64 * 64];

    const int tid = threadIdx.x;
    const size_t rowBase = (size_t)blockIdx.x * 64;

    // Stage X tile and full W into smem (float4, coalesced)
    {
        const float4* xs = (const float4*)(X + rowBase * HD);
        const float4* ws = (const float4*)W;
        float4* Xd = (float4*)Xs;
        float4* Wd = (float4*)Ws;
#pragma unroll
        for (int i = 0; i < 4; i++) {
            Xd[tid + i * 256] = xs[tid + i * 256];
            Wd[tid + i * 256] = ws[tid + i * 256];
        }
    }
    __syncthreads();

    const int tr = tid >> 4;    // 0..15 -> rows tr*4..tr*4+3
    const int tc = tid & 15;    // 0..15 -> cols tc*4..tc*4+3

    float acc[4][4] = {};
#pragma unroll
    for (int k = 0; k < 64; k += 4) {
        float4 a[4], b[4];
#pragma unroll
        for (int i = 0; i < 4; i++) a[i] = *(const float4*)&Xs[(tr * 4 + i) * 64 + k];
#pragma unroll
        for (int j = 0; j < 4; j++) b[j] = *(const float4*)&Ws[(tc * 4 + j) * 64 + k];
#pragma unroll
        for (int i = 0; i < 4; i++)
#pragma unroll
            for (int j = 0; j < 4; j++)
                acc[i][j] += a[i].x * b[j].x + a[i].y * b[j].y +
                             a[i].z * b[j].z + a[i].w * b[j].w;
    }

    const float4 bv = *(const float4*)&bias[tc * 4];
    const float bb[4] = {bv.x, bv.y, bv.z, bv.w};

    if (which == 1) {
        // Transposed store: g_k[(bh*64 + e)*1024 + s]
        const int bh = (int)(rowBase >> 10);          // 1024 rows per bh
        const int s0 = (int)(rowBase & 1023);
#pragma unroll
        for (int j = 0; j < 4; j++) {
            float4 o;
            o.x = fmaxf(acc[0][j] + bb[j], 0.0f);
            o.y = fmaxf(acc[1][j] + bb[j], 0.0f);
            o.z = fmaxf(acc[2][j] + bb[j], 0.0f);
            o.w = fmaxf(acc[3][j] + bb[j], 0.0f);
            *(float4*)&g_k[((size_t)bh * 64 + tc * 4 + j) * 1024 + s0 + tr * 4] = o;
        }
    } else {
#pragma unroll
        for (int i = 0; i < 4; i++) {
            float4 o;
            o.x = fmaxf(acc[i][0] + bb[0], 0.0f);
            o.y = fmaxf(acc[i][1] + bb[1], 0.0f);
            o.z = fmaxf(acc[i][2] + bb[2], 0.0f);
            o.w = fmaxf(acc[i][3] + bb[3], 0.0f);
            *(float4*)&Y[(rowBase + tr * 4 + i) * HD + tc * 4] = o;
        }
    }
}

// ---------------------------------------------------------------------------
// Attention: flash-style online softmax per (bh, 64-query tile).
//   score = softmax(q k^T / 8); a = score v
// K is pre-transposed in gmem -> smem K tile is [d][s_local], so the QK
// inner loop's B-reads are phase-consecutive (conflict-free), matching PV.
// Epilogue applies the reference's transpose(0,1,3,2)+reshape mangle and adds
// the raw-queries residual:  out[bh][lin] = a[lin & 1023][lin >> 10] + q_in[bh][lin]
// Static smem = exactly 48KB: Qs | KP (Kt, later reused for P) | Vs.
// ---------------------------------------------------------------------------
__global__ __launch_bounds__(256) void attn_kernel(
    const float* __restrict__ queries_in, float* __restrict__ out)
{
    __shared__ __align__(16) float smem[12288];   // 48 KB
    float* Qs = smem;            // 64x64 (pre-scaled by 1/8)
    float* KP = smem + 4096;     // 64x64 : K^T tile [d][s_local], then P tile
    float* Vs = smem + 8192;     // 64x64
    float* As = smem;            // 64x65 = 4160 floats (overlaps Qs + KP[0:64])

    const int tid = threadIdx.x;
    const int tr = tid >> 4;
    const int tc = tid & 15;
    const int bh = blockIdx.y;
    const int qbase = blockIdx.x * 64;
    const size_t base = (size_t)bh * (SEQ * HD);

    // Load Q tile, folding in the 1/sqrt(64) softmax scale
    {
        const float4* src = (const float4*)(g_q + base + (size_t)qbase * HD);
        float4* dst = (float4*)Qs;
#pragma unroll
        for (int i = 0; i < 4; i++) {
            float4 t = src[tid + i * 256];
            t.x *= 0.125f; t.y *= 0.125f; t.z *= 0.125f; t.w *= 0.125f;
            dst[tid + i * 256] = t;
        }
    }

    float m[4], l[4], o[4][4];
#pragma unroll
    for (int i = 0; i < 4; i++) {
        m[i] = -1e30f; l[i] = 0.0f;
#pragma unroll
        for (int j = 0; j < 4; j++) o[i][j] = 0.0f;
    }

    for (int kt = 0; kt < 16; kt++) {
        __syncthreads();   // previous iteration's PV reads of KP/Vs done
        {
            // K^T tile: KP[d][sl] = g_k[bh*64K + d*1024 + kt*64 + sl]
            const float* ktp = g_k + base + (size_t)kt * 64;
            const float4* vs = (const float4*)(g_v + base + (size_t)kt * 64 * HD);
            float4* vd = (float4*)Vs;
#pragma unroll
            for (int i = 0; i < 4; i++) {
                const int idx = tid + i * 256;       // 0..1023
                const int row = idx >> 4;            // d
                const int cg  = idx & 15;            // s_local group
                *(float4*)&KP[row * 64 + cg * 4] =
                    *(const float4*)&ktp[(size_t)row * 1024 + cg * 4];
                vd[idx] = vs[idx];
            }
        }
        __syncthreads();

        // p[i][j] = sum_d Qs[tr*4+i][d] * Kt[d][tc*4+j]   (both operands conflict-free)
        float p[4][4] = {};
#pragma unroll 4
        for (int k = 0; k < 64; k += 4) {
            const float4 b0 = *(const float4*)&KP[(k + 0) * 64 + tc * 4];
            const float4 b1 = *(const float4*)&KP[(k + 1) * 64 + tc * 4];
            const float4 b2 = *(const float4*)&KP[(k + 2) * 64 + tc * 4];
            const float4 b3 = *(const float4*)&KP[(k + 3) * 64 + tc * 4];
#pragma unroll
            for (int i = 0; i < 4; i++) {
                const float4 a = *(const float4*)&Qs[(tr * 4 + i) * 64 + k];
                p[i][0] += a.x * b0.x + a.y * b1.x + a.z * b2.x + a.w * b3.x;
                p[i][1] += a.x * b0.y + a.y * b1.y + a.z * b2.y + a.w * b3.y;
                p[i][2] += a.x * b0.z + a.y * b1.z + a.z * b2.z + a.w * b3.z;
                p[i][3] += a.x * b0.w + a.y * b1.w + a.z * b2.w + a.w * b3.w;
            }
        }
        __syncthreads();   // everyone done reading KP (Kt) before P overwrites it

        // Online softmax update (rows tr*4+i live on the 16-lane group tc=0..15)
#pragma unroll
        for (int i = 0; i < 4; i++) {
            float tmax = fmaxf(fmaxf(p[i][0], p[i][1]), fmaxf(p[i][2], p[i][3]));
#pragma unroll
            for (int off = 8; off >= 1; off >>= 1)
                tmax = fmaxf(tmax, __shfl_xor_sync(0xffffffffu, tmax, off, 16));
            const float mn = fmaxf(m[i], tmax);
            const float al = __expf(m[i] - mn);
            float tsum = 0.0f;
#pragma unroll
            for (int j = 0; j < 4; j++) { p[i][j] = __expf(p[i][j] - mn); tsum += p[i][j]; }
#pragma unroll
            for (int off = 8; off >= 1; off >>= 1)
                tsum += __shfl_xor_sync(0xffffffffu, tsum, off, 16);
            l[i] = l[i] * al + tsum;
            m[i] = mn;
#pragma unroll
            for (int j = 0; j < 4; j++) o[i][j] *= al;
            *(float4*)&KP[(tr * 4 + i) * 64 + tc * 4] =
                make_float4(p[i][0], p[i][1], p[i][2], p[i][3]);
        }
        __syncthreads();

        // o[i][j] += sum_k P[tr*4+i][k] * V[k][tc*4+j]
#pragma unroll 4
        for (int k = 0; k < 64; k += 4) {
            const float4 v0 = *(const float4*)&Vs[(k + 0) * 64 + tc * 4];
            const float4 v1 = *(const float4*)&Vs[(k + 1) * 64 + tc * 4];
            const float4 v2 = *(const float4*)&Vs[(k + 2) * 64 + tc * 4];
            const float4 v3 = *(const float4*)&Vs[(k + 3) * 64 + tc * 4];
#pragma unroll
            for (int i = 0; i < 4; i++) {
                const float4 pi = *(const float4*)&KP[(tr * 4 + i) * 64 + k];
                o[i][0] += pi.x * v0.x + pi.y * v1.x + pi.z * v2.x + pi.w * v3.x;
                o[i][1] += pi.x * v0.y + pi.y * v1.y + pi.z * v2.y + pi.w * v3.y;
                o[i][2] += pi.x * v0.z + pi.y * v1.z + pi.z * v2.z + pi.w * v3.z;
                o[i][3] += pi.x * v0.w + pi.y * v1.w + pi.z * v2.w + pi.w * v3.w;
            }
        }
    }

    __syncthreads();   // last PV reads of KP done before As overwrites Qs/KP head

    // Normalize and stage into As (stride 65 -> conflict-free transpose reads)
#pragma unroll
    for (int i = 0; i < 4; i++) {
        const float inv = 1.0f / l[i];
#pragma unroll
        for (int j = 0; j < 4; j++)
            As[(tr * 4 + i) * 65 + tc * 4 + j] = o[i][j] * inv;
    }
    __syncthreads();

    // out[bh][lin] = a[s = lin&1023][d = lin>>10] + queries_in[bh][lin],
    // restricted to s in [qbase, qbase+64): lin = d*1024 + qbase + sl
    const float* qin = queries_in + (size_t)bh * (SEQ * HD);
    float* op = out + (size_t)bh * (SEQ * HD);
#pragma unroll
    for (int t = 0; t < 16; t++) {
        const int idx = tid + t * 256;       // 0..4095
        const int d  = idx >> 6;
        const int sl = idx & 63;
        const int lin = d * 1024 + qbase + sl;
        op[lin] = As[sl * 65 + d] + qin[lin];
    }
}

// ---------------------------------------------------------------------------
// Launch: inputs in metadata order:
//  0 queries, 1 keys, 2 values, 3 Wq_w, 4 Wq_b, 5 Wk_w, 6 Wk_b, 7 Wv_w, 8 Wv_b
// ---------------------------------------------------------------------------
extern "C" void kernel_launch(void* const* d_in, const int* in_sizes, int n_in,
                              void* d_out, int out_size)
{
    const float* q  = (const float*)d_in[0];
    const float* k  = (const float*)d_in[1];
    const float* v  = (const float*)d_in[2];
    const float* Wq = (const float*)d_in[3];
    const float* bq = (const float*)d_in[4];
    const float* Wk = (const float*)d_in[5];
    const float* bk = (const float*)d_in[6];
    const float* Wv = (const float*)d_in[7];
    const float* bv = (const float*)d_in[8];
    float* out = (float*)d_out;

    proj_kernel<<<1024, 256>>>(q, Wq, bq, 0);
    proj_kernel<<<1024, 256>>>(k, Wk, bk, 1);
    proj_kernel<<<1024, 256>>>(v, Wv, bv, 2);
    attn_kernel<<<dim3(16, 64), 256>>>(q, out);
}

// round 6
// speedup vs baseline: 3.1810x; 1.5575x over previous
#include <cuda_runtime.h>

// Problem constants: B=8, H=8, S=1024, D=64
#define BH      64
#define SEQ     1024
#define HD      64
#define NROWS   (BH * SEQ)          // 65536 total (b,h,s) rows

// Scratch for projected q/k/v (allocation-free rule: __device__ globals)
// g_q, g_v: [bh][s][d] row-major.  g_k: TRANSPOSED, [bh][d][s].
__device__ float g_q[NROWS * HD];
__device__ float g_k[NROWS * HD];
__device__ float g_v[NROWS * HD];

typedef unsigned long long u64;

// ---- packed fp32x2 helpers (Blackwell FFMA2: full fp32, 2x throughput) ----
__device__ __forceinline__ u64 pack2(float x) {
    u64 r; asm("mov.b64 %0, {%1, %1};" : "=l"(r) : "f"(x)); return r;
}
__device__ __forceinline__ u64 pack2f(float lo, float hi) {
    u64 r; asm("mov.b64 %0, {%1, %2};" : "=l"(r) : "f"(lo), "f"(hi)); return r;
}
__device__ __forceinline__ float2 unpk(u64 v) {
    float2 f; asm("mov.b64 {%0, %1}, %2;" : "=f"(f.x), "=f"(f.y) : "l"(v)); return f;
}
__device__ __forceinline__ void fma2(u64& d, u64 a, u64 b) {
    asm("fma.rn.f32x2 %0, %1, %2, %0;" : "+l"(d) : "l"(a), "l"(b));
}
__device__ __forceinline__ u64 mul2(u64 a, u64 b) {
    u64 d; asm("mul.rn.f32x2 %0, %1, %2;" : "=l"(d) : "l"(a), "l"(b)); return d;
}

// ---------------------------------------------------------------------------
// Fused projections: Y[r][e] = relu( sum_d X[r][d] * W[e][d] + bias[e] )
// grid (512, 3): blockIdx.y selects q/k/v. 128 rows x 64 outputs per block.
// 256 threads, 8x4 micro-tile, f32x2 packed FMAs (pairs along output col).
// W is staged TRANSPOSED in smem (Wt[d][e]) so col-pairs are contiguous.
// which==1 (K) stores the result transposed per (b,h): g_k[bh][e][s].
// ---------------------------------------------------------------------------
__global__ __launch_bounds__(256) void proj_kernel(
    const float* __restrict__ Xq, const float* __restrict__ Xk,
    const float* __restrict__ Xv,
    const float* __restrict__ Wq, const float* __restrict__ bq,
    const float* __restrict__ Wk, const float* __restrict__ bk,
    const float* __restrict__ Wv, const float* __restrict__ bv)
{
    const int which = blockIdx.y;
    const float* __restrict__ X    = (which == 0) ? Xq : (which == 1) ? Xk : Xv;
    const float* __restrict__ W    = (which == 0) ? Wq : (which == 1) ? Wk : Wv;
    const float* __restrict__ bias = (which == 0) ? bq : (which == 1) ? bk : bv;
    float* __restrict__ Y = (which == 0) ? g_q : (which == 1) ? g_k : g_v;

    __shared__ __align__(16) float Xs[128 * 64];   // 32 KB
    __shared__ __align__(16) float Ws[64 * 64];    // 16 KB, TRANSPOSED: Wt[d][e]

    const int tid = threadIdx.x;
    const size_t rowBase = (size_t)blockIdx.x * 128;

    // Stage X tile (coalesced float4)
    {
        const float4* xs = (const float4*)(X + rowBase * HD);
        float4* Xd = (float4*)Xs;
#pragma unroll
        for (int i = 0; i < 8; i++) Xd[tid + i * 256] = xs[tid + i * 256];
    }
    // Stage W transposed: Wt[d][e] = W[e][d]. STS conflict-free (e consecutive
    // per warp); LDG scattered but W is 16KB and L2-resident.
#pragma unroll
    for (int i = 0; i < 4; i++) {
        const int idx = tid + i * 256;      // 0..1023
        const int e  = idx & 63;
        const int d4 = idx >> 6;            // 0..15
        const float4 w = *(const float4*)&W[e * 64 + d4 * 4];
        Ws[(d4 * 4 + 0) * 64 + e] = w.x;
        Ws[(d4 * 4 + 1) * 64 + e] = w.y;
        Ws[(d4 * 4 + 2) * 64 + e] = w.z;
        Ws[(d4 * 4 + 3) * 64 + e] = w.w;
    }
    __syncthreads();

    const int tr = tid >> 4;    // 0..15 -> rows tr*8 .. tr*8+7
    const int tc = tid & 15;    // cols tc*4 .. tc*4+3

    u64 acc[8][2];
#pragma unroll
    for (int i = 0; i < 8; i++) { acc[i][0] = 0ull; acc[i][1] = 0ull; }

#pragma unroll 4
    for (int k = 0; k < 64; k += 4) {
        u64 b[4][2];
#pragma unroll
        for (int kk = 0; kk < 4; kk++) {
            const float4 bb = *(const float4*)&Ws[(k + kk) * 64 + tc * 4];
            b[kk][0] = pack2f(bb.x, bb.y);
            b[kk][1] = pack2f(bb.z, bb.w);
        }
#pragma unroll
        for (int i = 0; i < 8; i++) {
            const float4 a = *(const float4*)&Xs[(tr * 8 + i) * 64 + k];
            u64 ap;
            ap = pack2(a.x); fma2(acc[i][0], ap, b[0][0]); fma2(acc[i][1], ap, b[0][1]);
            ap = pack2(a.y); fma2(acc[i][0], ap, b[1][0]); fma2(acc[i][1], ap, b[1][1]);
            ap = pack2(a.z); fma2(acc[i][0], ap, b[2][0]); fma2(acc[i][1], ap, b[2][1]);
            ap = pack2(a.w); fma2(acc[i][0], ap, b[3][0]); fma2(acc[i][1], ap, b[3][1]);
        }
    }

    const float4 bv4 = *(const float4*)&bias[tc * 4];
    float r[8][4];
#pragma unroll
    for (int i = 0; i < 8; i++) {
        const float2 c01 = unpk(acc[i][0]);
        const float2 c23 = unpk(acc[i][1]);
        r[i][0] = fmaxf(c01.x + bv4.x, 0.0f);
        r[i][1] = fmaxf(c01.y + bv4.y, 0.0f);
        r[i][2] = fmaxf(c23.x + bv4.z, 0.0f);
        r[i][3] = fmaxf(c23.y + bv4.w, 0.0f);
    }

    if (which == 1) {
        // Transposed store: g_k[(bh*64 + e)*1024 + s]; 8 consecutive s per thread
        const int bh = (int)(rowBase >> 10);
        const int s0 = (int)(rowBase & 1023);
#pragma unroll
        for (int j = 0; j < 4; j++) {
            float* dst = &Y[((size_t)bh * 64 + tc * 4 + j) * 1024 + s0 + tr * 8];
            *(float4*)dst       = make_float4(r[0][j], r[1][j], r[2][j], r[3][j]);
            *(float4*)(dst + 4) = make_float4(r[4][j], r[5][j], r[6][j], r[7][j]);
        }
    } else {
#pragma unroll
        for (int i = 0; i < 8; i++)
            *(float4*)&Y[(rowBase + tr * 8 + i) * HD + tc * 4] =
                make_float4(r[i][0], r[i][1], r[i][2], r[i][3]);
    }
}

// ---------------------------------------------------------------------------
// Attention: flash-style online softmax, 64 queries x 64 keys per tile.
// 128 threads, 8 rows x 4 cols micro-tile, f32x2 packed FMAs.
// Kt layout [d][s] -> QK col-pairs contiguous; V [s][d] -> PV col-pairs
// contiguous; broadcast operand gets a 1-MOV pack (ALU pipe).
// Epilogue applies the reference's transpose(0,1,3,2)+reshape mangle + residual.
// Static smem 48KB: Qs | KP (Kt then P) | Vs; As (64x65) overlays Qs at end.
// ---------------------------------------------------------------------------
__global__ __launch_bounds__(128, 4) void attn_kernel(
    const float* __restrict__ queries_in, float* __restrict__ out)
{
    __shared__ __align__(16) float smem[12288];   // 48 KB
    float* Qs = smem;            // 64x64 (pre-scaled by 1/8)
    float* KP = smem + 4096;     // 64x64 : Kt tile [d][s_local], then P tile
    float* Vs = smem + 8192;     // 64x64
    float* As = smem;            // 64x65 (overlaps Qs + KP[0:64])

    const int tid = threadIdx.x;
    const int tr = tid >> 4;     // 0..7 -> rows tr*8 .. tr*8+7
    const int tc = tid & 15;     // cols tc*4 .. tc*4+3
    const int bh = blockIdx.y;
    const int qbase = blockIdx.x * 64;
    const size_t base = (size_t)bh * (SEQ * HD);

    // Load Q tile, folding in the 1/sqrt(64) softmax scale
    {
        const float4* src = (const float4*)(g_q + base + (size_t)qbase * HD);
        float4* dst = (float4*)Qs;
#pragma unroll
        for (int i = 0; i < 8; i++) {
            float4 t = src[tid + i * 128];
            t.x *= 0.125f; t.y *= 0.125f; t.z *= 0.125f; t.w *= 0.125f;
            dst[tid + i * 128] = t;
        }
    }

    float m_[8], l_[8];
    u64 o2[8][2];
#pragma unroll
    for (int i = 0; i < 8; i++) {
        m_[i] = -1e30f; l_[i] = 0.0f; o2[i][0] = 0ull; o2[i][1] = 0ull;
    }

    for (int kt = 0; kt < 16; kt++) {
        __syncthreads();   // previous iteration's PV reads of KP/Vs done
        {
            // Kt tile: KP[d][sl] = g_k[base + d*1024 + kt*64 + sl]
            const float* ktp = g_k + base + (size_t)kt * 64;
            const float4* vs = (const float4*)(g_v + base + (size_t)kt * 64 * HD);
            float4* vd = (float4*)Vs;
#pragma unroll
            for (int i = 0; i < 8; i++) {
                const int idx = tid + i * 128;       // 0..1023
                const int row = idx >> 4;            // d
                const int cg  = idx & 15;            // s_local group
                *(float4*)&KP[row * 64 + cg * 4] =
                    *(const float4*)&ktp[(size_t)row * 1024 + cg * 4];
                vd[idx] = vs[idx];
            }
        }
        __syncthreads();

        // p[i][j] = sum_d Qs[tr*8+i][d] * Kt[d][tc*4+j]
        u64 p2[8][2];
#pragma unroll
        for (int i = 0; i < 8; i++) { p2[i][0] = 0ull; p2[i][1] = 0ull; }

#pragma unroll 4
        for (int k = 0; k < 64; k += 4) {
            u64 b[4][2];
#pragma unroll
            for (int kk = 0; kk < 4; kk++) {
                const float4 bb = *(const float4*)&KP[(k + kk) * 64 + tc * 4];
                b[kk][0] = pack2f(bb.x, bb.y);
                b[kk][1] = pack2f(bb.z, bb.w);
            }
#pragma unroll
            for (int i = 0; i < 8; i++) {
                const float4 a = *(const float4*)&Qs[(tr * 8 + i) * 64 + k];
                u64 ap;
                ap = pack2(a.x); fma2(p2[i][0], ap, b[0][0]); fma2(p2[i][1], ap, b[0][1]);
                ap = pack2(a.y); fma2(p2[i][0], ap, b[1][0]); fma2(p2[i][1], ap, b[1][1]);
                ap = pack2(a.z); fma2(p2[i][0], ap, b[2][0]); fma2(p2[i][1], ap, b[2][1]);
                ap = pack2(a.w); fma2(p2[i][0], ap, b[3][0]); fma2(p2[i][1], ap, b[3][1]);
            }
        }
        __syncthreads();   // all warps done reading KP (Kt) before P overwrites it

        // Online softmax update (row r's 64 scores live on the 16 lanes of tr=r/8)
#pragma unroll
        for (int i = 0; i < 8; i++) {
            const float2 x01 = unpk(p2[i][0]);
            const float2 x23 = unpk(p2[i][1]);
            float s0 = x01.x, s1 = x01.y, s2 = x23.x, s3 = x23.y;
            float tmax = fmaxf(fmaxf(s0, s1), fmaxf(s2, s3));
#pragma unroll
            for (int off = 8; off >= 1; off >>= 1)
                tmax = fmaxf(tmax, __shfl_xor_sync(0xffffffffu, tmax, off, 16));
            const float mn = fmaxf(m_[i], tmax);
            const float al = __expf(m_[i] - mn);
            s0 = __expf(s0 - mn); s1 = __expf(s1 - mn);
            s2 = __expf(s2 - mn); s3 = __expf(s3 - mn);
            float tsum = s0 + s1 + s2 + s3;
#pragma unroll
            for (int off = 8; off >= 1; off >>= 1)
                tsum += __shfl_xor_sync(0xffffffffu, tsum, off, 16);
            l_[i] = l_[i] * al + tsum;
            m_[i] = mn;
            const u64 alp = pack2(al);
            o2[i][0] = mul2(o2[i][0], alp);
            o2[i][1] = mul2(o2[i][1], alp);
            *(float4*)&KP[(tr * 8 + i) * 64 + tc * 4] = make_float4(s0, s1, s2, s3);
        }
        __syncthreads();

        // o[i][j] += sum_k P[tr*8+i][k] * V[k][tc*4+j]
#pragma unroll 4
        for (int k = 0; k < 64; k += 4) {
            u64 v[4][2];
#pragma unroll
            for (int kk = 0; kk < 4; kk++) {
                const float4 vv = *(const float4*)&Vs[(k + kk) * 64 + tc * 4];
                v[kk][0] = pack2f(vv.x, vv.y);
                v[kk][1] = pack2f(vv.z, vv.w);
            }
#pragma unroll
            for (int i = 0; i < 8; i++) {
                const float4 pp = *(const float4*)&KP[(tr * 8 + i) * 64 + k];
                u64 ap;
                ap = pack2(pp.x); fma2(o2[i][0], ap, v[0][0]); fma2(o2[i][1], ap, v[0][1]);
                ap = pack2(pp.y); fma2(o2[i][0], ap, v[1][0]); fma2(o2[i][1], ap, v[1][1]);
                ap = pack2(pp.z); fma2(o2[i][0], ap, v[2][0]); fma2(o2[i][1], ap, v[2][1]);
                ap = pack2(pp.w); fma2(o2[i][0], ap, v[3][0]); fma2(o2[i][1], ap, v[3][1]);
            }
        }
    }

    __syncthreads();   // last PV reads of KP done before As overwrites Qs/KP head

    // Normalize and stage into As (stride 65 -> conflict-free transpose reads)
#pragma unroll
    for (int i = 0; i < 8; i++) {
        const float inv = 1.0f / l_[i];
        const float2 a01 = unpk(o2[i][0]);
        const float2 a23 = unpk(o2[i][1]);
        float* dst = &As[(tr * 8 + i) * 65 + tc * 4];
        dst[0] = a01.x * inv;
        dst[1] = a01.y * inv;
        dst[2] = a23.x * inv;
        dst[3] = a23.y * inv;
    }
    __syncthreads();

    // out[bh][lin] = a[s = lin&1023][d = lin>>10] + queries_in[bh][lin],
    // restricted to s in [qbase, qbase+64): lin = d*1024 + qbase + sl
    const float* qin = queries_in + (size_t)bh * (SEQ * HD);
    float* op = out + (size_t)bh * (SEQ * HD);
#pragma unroll
    for (int t = 0; t < 32; t++) {
        const int idx = tid + t * 128;       // 0..4095
        const int d  = idx >> 6;
        const int sl = idx & 63;
        const int lin = d * 1024 + qbase + sl;
        op[lin] = As[sl * 65 + d] + qin[lin];
    }
}

// ---------------------------------------------------------------------------
// Launch: inputs in metadata order:
//  0 queries, 1 keys, 2 values, 3 Wq_w, 4 Wq_b, 5 Wk_w, 6 Wk_b, 7 Wv_w, 8 Wv_b
// ---------------------------------------------------------------------------
extern "C" void kernel_launch(void* const* d_in, const int* in_sizes, int n_in,
                              void* d_out, int out_size)
{
    const float* q  = (const float*)d_in[0];
    const float* k  = (const float*)d_in[1];
    const float* v  = (const float*)d_in[2];
    const float* Wq = (const float*)d_in[3];
    const float* bq = (const float*)d_in[4];
    const float* Wk = (const float*)d_in[5];
    const float* bk = (const float*)d_in[6];
    const float* Wv = (const float*)d_in[7];
    const float* bv = (const float*)d_in[8];
    float* out = (float*)d_out;

    proj_kernel<<<dim3(512, 3), 256>>>(q, k, v, Wq, bq, Wk, bk, Wv, bv);
    attn_kernel<<<dim3(16, 64), 128>>>(q, out);
}

// round 8
// speedup vs baseline: 6.5346x; 2.0543x over previous
#include <cuda_runtime.h>
#include <cuda_bf16.h>
#include <cstdint>

// Problem constants: B=8, H=8, S=1024, D=64
#define BH      64
#define SEQ     1024
#define HD      64
#define NROWS   (BH * SEQ)

typedef unsigned long long u64;

// ---------------------------------------------------------------------------
// Scratch (allocation-free rule: __device__ globals)
// q/k: [bh][s][d] bf16 hi/lo.   v: TRANSPOSED [bh][d][s] bf16 hi/lo.
// ---------------------------------------------------------------------------
__device__ __nv_bfloat16 g_qhi[NROWS * HD];
__device__ __nv_bfloat16 g_qlo[NROWS * HD];
__device__ __nv_bfloat16 g_khi[NROWS * HD];
__device__ __nv_bfloat16 g_klo[NROWS * HD];
__device__ __nv_bfloat16 g_vhi[NROWS * HD];
__device__ __nv_bfloat16 g_vlo[NROWS * HD];

// ---- packed fp32x2 helpers (FFMA2, full fp32) -----------------------------
__device__ __forceinline__ u64 pack2(float x) {
    u64 r; asm("mov.b64 %0, {%1, %1};" : "=l"(r) : "f"(x)); return r;
}
__device__ __forceinline__ u64 pack2f(float lo, float hi) {
    u64 r; asm("mov.b64 %0, {%1, %2};" : "=l"(r) : "f"(lo), "f"(hi)); return r;
}
__device__ __forceinline__ float2 unpk(u64 v) {
    float2 f; asm("mov.b64 {%0, %1}, %2;" : "=f"(f.x), "=f"(f.y) : "l"(v)); return f;
}
__device__ __forceinline__ void fma2(u64& d, u64 a, u64 b) {
    asm("fma.rn.f32x2 %0, %1, %2, %0;" : "+l"(d) : "l"(a), "l"(b));
}

__device__ __forceinline__ uint32_t smem_to_u32(const void* p) {
    uint32_t a;
    asm("{ .reg .u64 t; cvta.to.shared.u64 t, %1; cvt.u32.u64 %0, t; }"
        : "=r"(a) : "l"(p));
    return a;
}

// XOR swizzle for 128B rows: byte_off ^ ((byte_off>>3)&0x70)
#define SMEM_SWZ(off) ((uint32_t)(off) ^ (((uint32_t)(off) >> 3) & 0x70))

// ldmatrix x4 (non-transposed, b16)
#define LDSM_X4(r, addr) \
    asm volatile("ldmatrix.sync.aligned.m8n8.x4.shared.b16 {%0,%1,%2,%3}, [%4];" \
        : "=r"((r)[0]), "=r"((r)[1]), "=r"((r)[2]), "=r"((r)[3]) : "r"(addr))

// mma m16n8k16 bf16 (D,C fp32), C==D accumulate
__device__ __forceinline__ void mma_bf16(float c[4], const uint32_t a[4],
                                         uint32_t b0, uint32_t b1) {
    asm volatile(
        "mma.sync.aligned.m16n8k16.row.col.f32.bf16.bf16.f32 "
        "{%0,%1,%2,%3}, {%4,%5,%6,%7}, {%8,%9}, {%0,%1,%2,%3};"
        : "+f"(c[0]), "+f"(c[1]), "+f"(c[2]), "+f"(c[3])
        : "r"(a[0]), "r"(a[1]), "r"(a[2]), "r"(a[3]), "r"(b0), "r"(b1));
}

__device__ __forceinline__ void bsplit(float x, __nv_bfloat16& h, __nv_bfloat16& l) {
    h = __float2bfloat16(x);
    l = __float2bfloat16(x - __bfloat162float(h));
}
__device__ __forceinline__ uint32_t bpack(__nv_bfloat16 lo, __nv_bfloat16 hi) {
    __nv_bfloat162 t; t.x = lo; t.y = hi;
    return *(uint32_t*)&t;
}
__device__ __forceinline__ uint32_t bpackf(float a, float b) {
    __nv_bfloat162 t; t.x = __float2bfloat16(a); t.y = __float2bfloat16(b);
    return *(uint32_t*)&t;
}

// ---------------------------------------------------------------------------
// Fused projections (fp32 FFMA2 compute, bf16 hi/lo split outputs).
// grid (512, 3): y = q/k/v. 128 rows x 64 outputs per block, 256 threads.
// q: scaled by 1/8 (softmax scale folded). v: stored transposed [bh][d][s].
// ---------------------------------------------------------------------------
__global__ __launch_bounds__(256) void proj_kernel(
    const float* __restrict__ Xq, const float* __restrict__ Xk,
    const float* __restrict__ Xv,
    const float* __restrict__ Wq, const float* __restrict__ bq,
    const float* __restrict__ Wk, const float* __restrict__ bk,
    const float* __restrict__ Wv, const float* __restrict__ bv)
{
    const int which = blockIdx.y;
    const float* __restrict__ X    = (which == 0) ? Xq : (which == 1) ? Xk : Xv;
    const float* __restrict__ W    = (which == 0) ? Wq : (which == 1) ? Wk : Wv;
    const float* __restrict__ bias = (which == 0) ? bq : (which == 1) ? bk : bv;

    __shared__ __align__(16) float Xs[128 * 64];
    __shared__ __align__(16) float Ws[64 * 64];   // transposed Wt[d][e]

    const int tid = threadIdx.x;
    const size_t rowBase = (size_t)blockIdx.x * 128;

    {
        const float4* xs = (const float4*)(X + rowBase * HD);
        float4* Xd = (float4*)Xs;
#pragma unroll
        for (int i = 0; i < 8; i++) Xd[tid + i * 256] = xs[tid + i * 256];
    }
#pragma unroll
    for (int i = 0; i < 4; i++) {
        const int idx = tid + i * 256;
        const int e  = idx & 63;
        const int d4 = idx >> 6;
        const float4 w = *(const float4*)&W[e * 64 + d4 * 4];
        Ws[(d4 * 4 + 0) * 64 + e] = w.x;
        Ws[(d4 * 4 + 1) * 64 + e] = w.y;
        Ws[(d4 * 4 + 2) * 64 + e] = w.z;
        Ws[(d4 * 4 + 3) * 64 + e] = w.w;
    }
    __syncthreads();

    const int tr = tid >> 4;
    const int tc = tid & 15;

    u64 acc[8][2];
#pragma unroll
    for (int i = 0; i < 8; i++) { acc[i][0] = 0ull; acc[i][1] = 0ull; }

#pragma unroll 4
    for (int k = 0; k < 64; k += 4) {
        u64 b[4][2];
#pragma unroll
        for (int kk = 0; kk < 4; kk++) {
            const float4 bb = *(const float4*)&Ws[(k + kk) * 64 + tc * 4];
            b[kk][0] = pack2f(bb.x, bb.y);
            b[kk][1] = pack2f(bb.z, bb.w);
        }
#pragma unroll
        for (int i = 0; i < 8; i++) {
            const float4 a = *(const float4*)&Xs[(tr * 8 + i) * 64 + k];
            u64 ap;
            ap = pack2(a.x); fma2(acc[i][0], ap, b[0][0]); fma2(acc[i][1], ap, b[0][1]);
            ap = pack2(a.y); fma2(acc[i][0], ap, b[1][0]); fma2(acc[i][1], ap, b[1][1]);
            ap = pack2(a.z); fma2(acc[i][0], ap, b[2][0]); fma2(acc[i][1], ap, b[2][1]);
            ap = pack2(a.w); fma2(acc[i][0], ap, b[3][0]); fma2(acc[i][1], ap, b[3][1]);
        }
    }

    const float4 bv4 = *(const float4*)&bias[tc * 4];
    float r[8][4];
#pragma unroll
    for (int i = 0; i < 8; i++) {
        const float2 c01 = unpk(acc[i][0]);
        const float2 c23 = unpk(acc[i][1]);
        r[i][0] = fmaxf(c01.x + bv4.x, 0.0f);
        r[i][1] = fmaxf(c01.y + bv4.y, 0.0f);
        r[i][2] = fmaxf(c23.x + bv4.z, 0.0f);
        r[i][3] = fmaxf(c23.y + bv4.w, 0.0f);
    }
    if (which == 0) {   // fold 1/sqrt(64) into q
#pragma unroll
        for (int i = 0; i < 8; i++)
#pragma unroll
            for (int j = 0; j < 4; j++) r[i][j] *= 0.125f;
    }

    if (which == 2) {
        // V transposed: g_v*[(bh*64 + d)*1024 + s], 8 consecutive s per thread
        const int bh = (int)(rowBase >> 10);
        const int s0 = (int)(rowBase & 1023);
#pragma unroll
        for (int j = 0; j < 4; j++) {
            __nv_bfloat16 h8[8], l8[8];
#pragma unroll
            for (int i = 0; i < 8; i++) bsplit(r[i][j], h8[i], l8[i]);
            const size_t off = ((size_t)bh * 64 + tc * 4 + j) * 1024 + s0 + tr * 8;
            *(uint4*)&g_vhi[off] = *(uint4*)h8;
            *(uint4*)&g_vlo[off] = *(uint4*)l8;
        }
    } else {
        __nv_bfloat16* Yh = (which == 0) ? g_qhi : g_khi;
        __nv_bfloat16* Yl = (which == 0) ? g_qlo : g_klo;
#pragma unroll
        for (int i = 0; i < 8; i++) {
            __nv_bfloat16 h4[4], l4[4];
#pragma unroll
            for (int j = 0; j < 4; j++) bsplit(r[i][j], h4[j], l4[j]);
            const size_t off = (rowBase + tr * 8 + i) * HD + tc * 4;
            *(uint2*)&Yh[off] = *(uint2*)h4;
            *(uint2*)&Yl[off] = *(uint2*)l4;
        }
    }
}

// ---------------------------------------------------------------------------
// mma.sync bf16-split flash attention (no max-subtraction; scores bounded).
// One CTA = (bh, 64-query tile). 4 warps x 16 q-rows. Grid (16, 64).
// SMEM tiles (XOR-swizzled 128B rows): Khi|Klo [key][d], Vhi|Vlo [d][key].
// S/P never touch smem: QK C-fragment == PV A-fragment layout.
//
// Fragment layouts (PTX mma m16n8k16 row.col):
//   A (m16k16, row-major):  a0:(r=g,   k=2q+{0,1})  a1:(r=g+8, k=2q+{0,1})
//                           a2:(r=g,   k=2q+{8,9})  a3:(r=g+8, k=2q+{8,9})
//   B (k16n8, col-major):   b0:(k=2q+{0,1}, n=g)    b1:(k=2q+{8,9}, n=g)
//   C (m16n8 f32):          c0,c1:(r=g, n=2q,2q+1)  c2,c3:(r=g+8, same)
//   where g = lane>>2, q = lane&3.
// ldmatrix m8n8 gives thread: row lane>>2, cols 2(lane&3)+{0,1} -> matches
// both A (matrix rows = m-rows, cols = k) and B (matrix rows = n, cols = k).
// ---------------------------------------------------------------------------
__global__ __launch_bounds__(128) void attn_kernel(
    const float* __restrict__ queries_in, float* __restrict__ out)
{
    __shared__ __align__(16) char tiles_raw[32768 + 1024];

    const int tid  = threadIdx.x;
    const int lane = tid & 31;
    const int w    = tid >> 5;
    const int bh = blockIdx.y;
    const int qbase = blockIdx.x * 64;
    const size_t base = (size_t)bh * (SEQ * HD);

    const uint32_t raw32 = smem_to_u32(tiles_raw);
    const uint32_t t32 = (raw32 + 1023) & ~1023u;
    char* tp = tiles_raw + (t32 - raw32);
    float* As = (float*)tp;                 // 64x65 epilogue buffer (overlays tiles)

    // ldmatrix lane->address decomposition
    const int rowA = (lane & 7) + ((lane & 8)  ? 8 : 0);   // A: m-row within 16
    const int colA = (lane & 16) ? 16 : 0;                 // A: k byte offset (8 elems)
    const int rowB = (lane & 7) + ((lane & 16) ? 8 : 0);   // B: n-row within 16
    const int colB = (lane & 8)  ? 16 : 0;                 // B: k byte offset

    // ---- stage Q tile (hi at 0, lo at 8192), swizzled ----
    {
        const uint4* qh = (const uint4*)(g_qhi + base + (size_t)qbase * HD);
        const uint4* ql = (const uint4*)(g_qlo + base + (size_t)qbase * HD);
#pragma unroll
        for (int c = tid; c < 512; c += 128) {
            const uint32_t sw = SMEM_SWZ(c * 16);
            *(uint4*)(tp + sw)        = qh[c];
            *(uint4*)(tp + 8192 + sw) = ql[c];
        }
    }
    __syncthreads();

    // ---- Q fragments (persist in registers) ----
    uint32_t qh[4][4], ql[4][4];
#pragma unroll
    for (int kt2 = 0; kt2 < 4; kt2++) {
        const uint32_t off = SMEM_SWZ((w * 16 + rowA) * 128 + kt2 * 32 + colA);
        LDSM_X4(qh[kt2], t32 + off);
        LDSM_X4(ql[kt2], t32 + 8192 + off);
    }

    float oa[8][4];
#pragma unroll
    for (int i = 0; i < 8; i++)
#pragma unroll
        for (int j = 0; j < 4; j++) oa[i][j] = 0.0f;
    float lsum0 = 0.0f, lsum1 = 0.0f;

    for (int kt = 0; kt < 16; kt++) {
        __syncthreads();   // prior iter's ldmatrix reads (or Q frags) done
        {
            const uint4* kh = (const uint4*)(g_khi + base + (size_t)kt * 64 * HD);
            const uint4* kl = (const uint4*)(g_klo + base + (size_t)kt * 64 * HD);
            const __nv_bfloat16* vh = g_vhi + (size_t)bh * (HD * SEQ) + kt * 64;
            const __nv_bfloat16* vl = g_vlo + (size_t)bh * (HD * SEQ) + kt * 64;
#pragma unroll
            for (int c = tid; c < 512; c += 128) {
                const uint32_t sw = SMEM_SWZ(c * 16);
                *(uint4*)(tp + sw)        = kh[c];
                *(uint4*)(tp + 8192 + sw) = kl[c];
                const int row = c >> 3, cb = c & 7;   // V: row = d, 8 keys per chunk
                *(uint4*)(tp + 16384 + sw) = *(const uint4*)(vh + (size_t)row * SEQ + cb * 8);
                *(uint4*)(tp + 24576 + sw) = *(const uint4*)(vl + (size_t)row * SEQ + cb * 8);
            }
        }
        __syncthreads();

        // ---- S = Qhi*Khi + Qlo*Khi + Qhi*Klo ----
        float sa[8][4];
#pragma unroll
        for (int i = 0; i < 8; i++)
#pragma unroll
            for (int j = 0; j < 4; j++) sa[i][j] = 0.0f;

#pragma unroll
        for (int np = 0; np < 4; np++) {
#pragma unroll
            for (int kt2 = 0; kt2 < 4; kt2++) {
                const uint32_t off = SMEM_SWZ((np * 16 + rowB) * 128 + kt2 * 32 + colB);
                uint32_t bkh[4], bkl[4];
                LDSM_X4(bkh, t32 + off);
                LDSM_X4(bkl, t32 + 8192 + off);
                mma_bf16(sa[2 * np],     qh[kt2], bkh[0], bkh[1]);
                mma_bf16(sa[2 * np],     ql[kt2], bkh[0], bkh[1]);
                mma_bf16(sa[2 * np],     qh[kt2], bkl[0], bkl[1]);
                mma_bf16(sa[2 * np + 1], qh[kt2], bkh[2], bkh[3]);
                mma_bf16(sa[2 * np + 1], ql[kt2], bkh[2], bkh[3]);
                mma_bf16(sa[2 * np + 1], qh[kt2], bkl[2], bkl[3]);
            }
        }

        // ---- P = exp(S): row-sum accumulate + bf16 split into PV A-frags ----
        uint32_t phi[4][4], plo[4][4];
#pragma unroll
        for (int nt = 0; nt < 8; nt++) {
            const float e0 = __expf(sa[nt][0]);
            const float e1 = __expf(sa[nt][1]);
            const float e2 = __expf(sa[nt][2]);
            const float e3 = __expf(sa[nt][3]);
            lsum0 += e0 + e1;
            lsum1 += e2 + e3;
            __nv_bfloat16 h0, l0, h1, l1, h2, l2, h3, l3;
            bsplit(e0, h0, l0); bsplit(e1, h1, l1);
            bsplit(e2, h2, l2); bsplit(e3, h3, l3);
            const int kt2 = nt >> 1, sl = (nt & 1) * 2;
            phi[kt2][sl]     = bpack(h0, h1);
            phi[kt2][sl + 1] = bpack(h2, h3);
            plo[kt2][sl]     = bpack(l0, l1);
            plo[kt2][sl + 1] = bpack(l2, l3);
        }

        // ---- O += Phi*Vhi + Plo*Vhi + Phi*Vlo ----
#pragma unroll
        for (int np = 0; np < 4; np++) {
#pragma unroll
            for (int kt2 = 0; kt2 < 4; kt2++) {
                const uint32_t off = SMEM_SWZ((np * 16 + rowB) * 128 + kt2 * 32 + colB);
                uint32_t bvh[4], bvl[4];
                LDSM_X4(bvh, t32 + 16384 + off);
                LDSM_X4(bvl, t32 + 24576 + off);
                mma_bf16(oa[2 * np],     phi[kt2], bvh[0], bvh[1]);
                mma_bf16(oa[2 * np],     plo[kt2], bvh[0], bvh[1]);
                mma_bf16(oa[2 * np],     phi[kt2], bvl[0], bvl[1]);
                mma_bf16(oa[2 * np + 1], phi[kt2], bvh[2], bvh[3]);
                mma_bf16(oa[2 * np + 1], plo[kt2], bvh[2], bvh[3]);
                mma_bf16(oa[2 * np + 1], phi[kt2], bvl[2], bvl[3]);
            }
        }
    }

    // ---- finalize row sums (linear -> single quad reduction) ----
    lsum0 += __shfl_xor_sync(0xffffffffu, lsum0, 1);
    lsum0 += __shfl_xor_sync(0xffffffffu, lsum0, 2);
    lsum1 += __shfl_xor_sync(0xffffffffu, lsum1, 1);
    lsum1 += __shfl_xor_sync(0xffffffffu, lsum1, 2);
    const float inv0 = 1.0f / lsum0;
    const float inv1 = 1.0f / lsum1;

    __syncthreads();   // all ldmatrix reads done before As overwrites tiles

    // stage normalized O into As[s_local][d] (stride 65)
    {
        const int r0 = w * 16 + (lane >> 2);
        const int r1 = r0 + 8;
#pragma unroll
        for (int nt = 0; nt < 8; nt++) {
            const int d0 = nt * 8 + (lane & 3) * 2;
            As[r0 * 65 + d0]     = oa[nt][0] * inv0;
            As[r0 * 65 + d0 + 1] = oa[nt][1] * inv0;
            As[r1 * 65 + d0]     = oa[nt][2] * inv1;
            As[r1 * 65 + d0 + 1] = oa[nt][3] * inv1;
        }
    }
    __syncthreads();

    // out[bh][lin] = a[s = lin&1023][d = lin>>10] + queries_in[bh][lin]
    const float* qin = queries_in + base;
    float* op = out + base;
#pragma unroll
    for (int t = 0; t < 32; t++) {
        const int idx = tid + t * 128;       // 0..4095
        const int d  = idx >> 6;
        const int sl = idx & 63;
        const int lin = d * 1024 + qbase + sl;
        op[lin] = As[sl * 65 + d] + qin[lin];
    }
}

// ---------------------------------------------------------------------------
// Launch: inputs in metadata order:
//  0 queries, 1 keys, 2 values, 3 Wq_w, 4 Wq_b, 5 Wk_w, 6 Wk_b, 7 Wv_w, 8 Wv_b
// ---------------------------------------------------------------------------
extern "C" void kernel_launch(void* const* d_in, const int* in_sizes, int n_in,
                              void* d_out, int out_size)
{
    const float* q  = (const float*)d_in[0];
    const float* k  = (const float*)d_in[1];
    const float* v  = (const float*)d_in[2];
    const float* Wq = (const float*)d_in[3];
    const float* bq = (const float*)d_in[4];
    const float* Wk = (const float*)d_in[5];
    const float* bk = (const float*)d_in[6];
    const float* Wv = (const float*)d_in[7];
    const float* bv = (const float*)d_in[8];
    float* out = (float*)d_out;

    proj_kernel<<<dim3(512, 3), 256>>>(q, k, v, Wq, bq, Wk, bk, Wv, bv);
    attn_kernel<<<dim3(16, 64), 128>>>(q, out);
}

// round 9
// speedup vs baseline: 8.0171x; 1.2269x over previous
#include <cuda_runtime.h>
#include <cuda_bf16.h>
#include <cstdint>

// Problem constants: B=8, H=8, S=1024, D=64
#define BH      64
#define SEQ     1024
#define HD      64
#define NROWS   (BH * SEQ)

typedef unsigned long long u64;

// ---------------------------------------------------------------------------
// Scratch (allocation-free rule: __device__ globals)
// q/k: [bh][s][d] bf16 hi/lo.   v: TRANSPOSED [bh][d][s] bf16 hi/lo.
// ---------------------------------------------------------------------------
__device__ __nv_bfloat16 g_qhi[NROWS * HD];
__device__ __nv_bfloat16 g_qlo[NROWS * HD];
__device__ __nv_bfloat16 g_khi[NROWS * HD];
__device__ __nv_bfloat16 g_klo[NROWS * HD];
__device__ __nv_bfloat16 g_vhi[NROWS * HD];
__device__ __nv_bfloat16 g_vlo[NROWS * HD];

// ---- packed fp32x2 helpers (FFMA2, full fp32) -----------------------------
__device__ __forceinline__ u64 pack2(float x) {
    u64 r; asm("mov.b64 %0, {%1, %1};" : "=l"(r) : "f"(x)); return r;
}
__device__ __forceinline__ u64 pack2f(float lo, float hi) {
    u64 r; asm("mov.b64 %0, {%1, %2};" : "=l"(r) : "f"(lo), "f"(hi)); return r;
}
__device__ __forceinline__ float2 unpk(u64 v) {
    float2 f; asm("mov.b64 {%0, %1}, %2;" : "=f"(f.x), "=f"(f.y) : "l"(v)); return f;
}
__device__ __forceinline__ void fma2(u64& d, u64 a, u64 b) {
    asm("fma.rn.f32x2 %0, %1, %2, %0;" : "+l"(d) : "l"(a), "l"(b));
}

__device__ __forceinline__ uint32_t smem_to_u32(const void* p) {
    uint32_t a;
    asm("{ .reg .u64 t; cvta.to.shared.u64 t, %1; cvt.u32.u64 %0, t; }"
        : "=r"(a) : "l"(p));
    return a;
}

// XOR swizzle for 128B rows: byte_off ^ ((byte_off>>3)&0x70)
#define SMEM_SWZ(off) ((uint32_t)(off) ^ (((uint32_t)(off) >> 3) & 0x70))

// ---- cp.async (LDGSTS, sm_80+ base ISA) -----------------------------------
#define CP_ASYNC16(saddr, gptr) \
    asm volatile("cp.async.cg.shared.global [%0], [%1], 16;" \
        :: "r"((uint32_t)(saddr)), "l"(gptr) : "memory")
#define CP_COMMIT() asm volatile("cp.async.commit_group;" ::: "memory")
#define CP_WAIT(N)  asm volatile("cp.async.wait_group %0;" :: "n"(N) : "memory")

// ldmatrix x4 (non-transposed, b16)
#define LDSM_X4(r, addr) \
    asm volatile("ldmatrix.sync.aligned.m8n8.x4.shared.b16 {%0,%1,%2,%3}, [%4];" \
        : "=r"((r)[0]), "=r"((r)[1]), "=r"((r)[2]), "=r"((r)[3]) : "r"(addr))

// mma m16n8k16 bf16 (D,C fp32), C==D accumulate
__device__ __forceinline__ void mma_bf16(float c[4], const uint32_t a[4],
                                         uint32_t b0, uint32_t b1) {
    asm volatile(
        "mma.sync.aligned.m16n8k16.row.col.f32.bf16.bf16.f32 "
        "{%0,%1,%2,%3}, {%4,%5,%6,%7}, {%8,%9}, {%0,%1,%2,%3};"
        : "+f"(c[0]), "+f"(c[1]), "+f"(c[2]), "+f"(c[3])
        : "r"(a[0]), "r"(a[1]), "r"(a[2]), "r"(a[3]), "r"(b0), "r"(b1));
}

__device__ __forceinline__ void bsplit(float x, __nv_bfloat16& h, __nv_bfloat16& l) {
    h = __float2bfloat16(x);
    l = __float2bfloat16(x - __bfloat162float(h));
}
__device__ __forceinline__ uint32_t bpack(__nv_bfloat16 lo, __nv_bfloat16 hi) {
    __nv_bfloat162 t; t.x = lo; t.y = hi;
    return *(uint32_t*)&t;
}

// async K tile (hi+lo, 64 keys x 64 d, 128B rows, swizzled) -> one group
__device__ __forceinline__ void cp_tile_K(uint32_t dsthi, uint32_t dstlo,
                                          const uint4* kh, const uint4* kl,
                                          int tid) {
#pragma unroll
    for (int c = tid; c < 512; c += 128) {
        const uint32_t sw = SMEM_SWZ(c * 16);
        CP_ASYNC16(dsthi + sw, kh + c);
        CP_ASYNC16(dstlo + sw, kl + c);
    }
    CP_COMMIT();
}
// async V tile (hi+lo, 64 d-rows x 64 keys from [d][s] gmem) -> one group
__device__ __forceinline__ void cp_tile_V(uint32_t dsthi, uint32_t dstlo,
                                          const __nv_bfloat16* vh,
                                          const __nv_bfloat16* vl, int tid) {
#pragma unroll
    for (int c = tid; c < 512; c += 128) {
        const int row = c >> 3, cb = c & 7;
        const uint32_t sw = SMEM_SWZ(c * 16);
        CP_ASYNC16(dsthi + sw, (const uint4*)(vh + (size_t)row * SEQ) + cb);
        CP_ASYNC16(dstlo + sw, (const uint4*)(vl + (size_t)row * SEQ) + cb);
    }
    CP_COMMIT();
}

// ---------------------------------------------------------------------------
// Fused projections (fp32 FFMA2 compute, bf16 hi/lo split outputs).
// grid (512, 3): y = q/k/v. 128 rows x 64 outputs per block, 256 threads.
// q: scaled by 1/8 (softmax scale folded). v: stored transposed [bh][d][s].
// ---------------------------------------------------------------------------
__global__ __launch_bounds__(256) void proj_kernel(
    const float* __restrict__ Xq, const float* __restrict__ Xk,
    const float* __restrict__ Xv,
    const float* __restrict__ Wq, const float* __restrict__ bq,
    const float* __restrict__ Wk, const float* __restrict__ bk,
    const float* __restrict__ Wv, const float* __restrict__ bv)
{
    const int which = blockIdx.y;
    const float* __restrict__ X    = (which == 0) ? Xq : (which == 1) ? Xk : Xv;
    const float* __restrict__ W    = (which == 0) ? Wq : (which == 1) ? Wk : Wv;
    const float* __restrict__ bias = (which == 0) ? bq : (which == 1) ? bk : bv;

    __shared__ __align__(16) float Xs[128 * 64];
    __shared__ __align__(16) float Ws[64 * 64];   // transposed Wt[d][e]

    const int tid = threadIdx.x;
    const size_t rowBase = (size_t)blockIdx.x * 128;

    {
        const float4* xs = (const float4*)(X + rowBase * HD);
        float4* Xd = (float4*)Xs;
#pragma unroll
        for (int i = 0; i < 8; i++) Xd[tid + i * 256] = xs[tid + i * 256];
    }
#pragma unroll
    for (int i = 0; i < 4; i++) {
        const int idx = tid + i * 256;
        const int e  = idx & 63;
        const int d4 = idx >> 6;
        const float4 w = *(const float4*)&W[e * 64 + d4 * 4];
        Ws[(d4 * 4 + 0) * 64 + e] = w.x;
        Ws[(d4 * 4 + 1) * 64 + e] = w.y;
        Ws[(d4 * 4 + 2) * 64 + e] = w.z;
        Ws[(d4 * 4 + 3) * 64 + e] = w.w;
    }
    __syncthreads();

    const int tr = tid >> 4;
    const int tc = tid & 15;

    u64 acc[8][2];
#pragma unroll
    for (int i = 0; i < 8; i++) { acc[i][0] = 0ull; acc[i][1] = 0ull; }

#pragma unroll 4
    for (int k = 0; k < 64; k += 4) {
        u64 b[4][2];
#pragma unroll
        for (int kk = 0; kk < 4; kk++) {
            const float4 bb = *(const float4*)&Ws[(k + kk) * 64 + tc * 4];
            b[kk][0] = pack2f(bb.x, bb.y);
            b[kk][1] = pack2f(bb.z, bb.w);
        }
#pragma unroll
        for (int i = 0; i < 8; i++) {
            const float4 a = *(const float4*)&Xs[(tr * 8 + i) * 64 + k];
            u64 ap;
            ap = pack2(a.x); fma2(acc[i][0], ap, b[0][0]); fma2(acc[i][1], ap, b[0][1]);
            ap = pack2(a.y); fma2(acc[i][0], ap, b[1][0]); fma2(acc[i][1], ap, b[1][1]);
            ap = pack2(a.z); fma2(acc[i][0], ap, b[2][0]); fma2(acc[i][1], ap, b[2][1]);
            ap = pack2(a.w); fma2(acc[i][0], ap, b[3][0]); fma2(acc[i][1], ap, b[3][1]);
        }
    }

    const float4 bv4 = *(const float4*)&bias[tc * 4];
    float r[8][4];
#pragma unroll
    for (int i = 0; i < 8; i++) {
        const float2 c01 = unpk(acc[i][0]);
        const float2 c23 = unpk(acc[i][1]);
        r[i][0] = fmaxf(c01.x + bv4.x, 0.0f);
        r[i][1] = fmaxf(c01.y + bv4.y, 0.0f);
        r[i][2] = fmaxf(c23.x + bv4.z, 0.0f);
        r[i][3] = fmaxf(c23.y + bv4.w, 0.0f);
    }
    if (which == 0) {   // fold 1/sqrt(64) into q
#pragma unroll
        for (int i = 0; i < 8; i++)
#pragma unroll
            for (int j = 0; j < 4; j++) r[i][j] *= 0.125f;
    }

    if (which == 2) {
        // V transposed: g_v*[(bh*64 + d)*1024 + s], 8 consecutive s per thread
        const int bh = (int)(rowBase >> 10);
        const int s0 = (int)(rowBase & 1023);
#pragma unroll
        for (int j = 0; j < 4; j++) {
            __nv_bfloat16 h8[8], l8[8];
#pragma unroll
            for (int i = 0; i < 8; i++) bsplit(r[i][j], h8[i], l8[i]);
            const size_t off = ((size_t)bh * 64 + tc * 4 + j) * 1024 + s0 + tr * 8;
            *(uint4*)&g_vhi[off] = *(uint4*)h8;
            *(uint4*)&g_vlo[off] = *(uint4*)l8;
        }
    } else {
        __nv_bfloat16* Yh = (which == 0) ? g_qhi : g_khi;
        __nv_bfloat16* Yl = (which == 0) ? g_qlo : g_klo;
#pragma unroll
        for (int i = 0; i < 8; i++) {
            __nv_bfloat16 h4[4], l4[4];
#pragma unroll
            for (int j = 0; j < 4; j++) bsplit(r[i][j], h4[j], l4[j]);
            const size_t off = (rowBase + tr * 8 + i) * HD + tc * 4;
            *(uint2*)&Yh[off] = *(uint2*)h4;
            *(uint2*)&Yl[off] = *(uint2*)l4;
        }
    }
}

// ---------------------------------------------------------------------------
// mma.sync bf16-split flash attention, cp.async software-pipelined.
// One CTA = (bh, 64-query tile). 4 warps x 16 q-rows. Grid (16, 64).
//
// SMEM (48KB static, 128B-aligned; XOR-swizzled 128B rows):
//   [    0: 8192) Khi buf0     [ 8192:16384) Klo buf0
//   [16384:24576) Khi buf1     [24576:32768) Klo buf1   (also Q staging)
//   [32768:40960) Vhi          [40960:49152) Vlo
//   As (64x65 f32 epilogue) overlays [0:16640).
//
// Pipeline per iter kt:
//   sync (V-buffer reuse guard) ; issue V(kt) async
//   wait_group 1  -> K(kt) complete (V(kt) may pend; positional semantics)
//   sync ; QK(kt) from K buf[kt&1] ; issue K(kt+1) -> buf[~kt&1]
//   exp/pack ; wait_group (kt<15?1:0) -> V(kt) complete ; sync ; PV(kt)
//
// Fragment layouts (PTX mma m16n8k16 row.col), g = lane>>2, q = lane&3:
//   A: a0:(r=g,k=2q+{0,1}) a1:(r=g+8,...) a2:(r=g,k=2q+{8,9}) a3:(r=g+8,...)
//   B: b0:(k=2q+{0,1},n=g) b1:(k=2q+{8,9},n=g)
//   C: c0,c1:(r=g,n=2q,2q+1) c2,c3:(r=g+8,same)
// ---------------------------------------------------------------------------
__global__ __launch_bounds__(128) void attn_kernel(
    const float* __restrict__ queries_in, float* __restrict__ out)
{
    __shared__ __align__(128) char tiles[49152];

    const int tid  = threadIdx.x;
    const int lane = tid & 31;
    const int w    = tid >> 5;
    const int bh = blockIdx.y;
    const int qbase = blockIdx.x * 64;
    const size_t base = (size_t)bh * (SEQ * HD);
    const size_t vbase = (size_t)bh * (HD * SEQ);

    const uint32_t t32 = smem_to_u32(tiles);
    float* As = (float*)tiles;              // epilogue buffer overlays K buf0

    // ldmatrix lane->address decomposition
    const int rowA = (lane & 7) + ((lane & 8)  ? 8 : 0);
    const int colA = (lane & 16) ? 16 : 0;
    const int rowB = (lane & 7) + ((lane & 16) ? 8 : 0);
    const int colB = (lane & 8)  ? 16 : 0;

    // ---- prefetch K(0) into buf0 (group 0) ----
    cp_tile_K(t32, t32 + 8192,
              (const uint4*)(g_khi + base), (const uint4*)(g_klo + base), tid);

    // ---- stage Q tile into buf1 region (normal stores), swizzled ----
    {
        const uint4* qh = (const uint4*)(g_qhi + base + (size_t)qbase * HD);
        const uint4* ql = (const uint4*)(g_qlo + base + (size_t)qbase * HD);
#pragma unroll
        for (int c = tid; c < 512; c += 128) {
            const uint32_t sw = SMEM_SWZ(c * 16);
            *(uint4*)(tiles + 16384 + sw) = qh[c];
            *(uint4*)(tiles + 24576 + sw) = ql[c];
        }
    }
    __syncthreads();

    // ---- Q fragments (persist in registers); buf1 free after this + sync ----
    uint32_t qh[4][4], ql[4][4];
#pragma unroll
    for (int kt2 = 0; kt2 < 4; kt2++) {
        const uint32_t off = SMEM_SWZ((w * 16 + rowA) * 128 + kt2 * 32 + colA);
        LDSM_X4(qh[kt2], t32 + 16384 + off);
        LDSM_X4(ql[kt2], t32 + 24576 + off);
    }

    float oa[8][4];
#pragma unroll
    for (int i = 0; i < 8; i++)
#pragma unroll
        for (int j = 0; j < 4; j++) oa[i][j] = 0.0f;
    float lsum0 = 0.0f, lsum1 = 0.0f;

    for (int kt = 0; kt < 16; kt++) {
        const uint32_t kbhi = t32 + ((kt & 1) ? 16384u : 0u);
        const uint32_t kblo = kbhi + 8192;

        __syncthreads();   // PV(kt-1) V reads done / Q frags extracted
        cp_tile_V(t32 + 32768, t32 + 40960,
                  g_vhi + vbase + kt * 64, g_vlo + vbase + kt * 64, tid);
        CP_WAIT(1);        // K(kt) landed (only V(kt) may still pend)
        __syncthreads();

        // ---- S = Qhi*Khi + Qlo*Khi + Qhi*Klo ----
        float sa[8][4];
#pragma unroll
        for (int i = 0; i < 8; i++)
#pragma unroll
            for (int j = 0; j < 4; j++) sa[i][j] = 0.0f;

#pragma unroll
        for (int np = 0; np < 4; np++) {
#pragma unroll
            for (int kt2 = 0; kt2 < 4; kt2++) {
                const uint32_t off = SMEM_SWZ((np * 16 + rowB) * 128 + kt2 * 32 + colB);
                uint32_t bkh[4], bkl[4];
                LDSM_X4(bkh, kbhi + off);
                LDSM_X4(bkl, kblo + off);
                mma_bf16(sa[2 * np],     qh[kt2], bkh[0], bkh[1]);
                mma_bf16(sa[2 * np],     ql[kt2], bkh[0], bkh[1]);
                mma_bf16(sa[2 * np],     qh[kt2], bkl[0], bkl[1]);
                mma_bf16(sa[2 * np + 1], qh[kt2], bkh[2], bkh[3]);
                mma_bf16(sa[2 * np + 1], ql[kt2], bkh[2], bkh[3]);
                mma_bf16(sa[2 * np + 1], qh[kt2], bkl[2], bkl[3]);
            }
        }

        // ---- prefetch K(kt+1) into the other buffer ----
        if (kt < 15) {
            const uint32_t nbhi = t32 + ((kt & 1) ? 0u : 16384u);
            cp_tile_K(nbhi, nbhi + 8192,
                      (const uint4*)(g_khi + base + (size_t)(kt + 1) * 64 * HD),
                      (const uint4*)(g_klo + base + (size_t)(kt + 1) * 64 * HD), tid);
        }

        // ---- P = exp(S): row-sum accumulate + bf16 split into PV A-frags ----
        uint32_t phi[4][4], plo[4][4];
#pragma unroll
        for (int nt = 0; nt < 8; nt++) {
            const float e0 = __expf(sa[nt][0]);
            const float e1 = __expf(sa[nt][1]);
            const float e2 = __expf(sa[nt][2]);
            const float e3 = __expf(sa[nt][3]);
            lsum0 += e0 + e1;
            lsum1 += e2 + e3;
            __nv_bfloat16 h0, l0, h1, l1, h2, l2, h3, l3;
            bsplit(e0, h0, l0); bsplit(e1, h1, l1);
            bsplit(e2, h2, l2); bsplit(e3, h3, l3);
            const int kt2 = nt >> 1, sl = (nt & 1) * 2;
            phi[kt2][sl]     = bpack(h0, h1);
            phi[kt2][sl + 1] = bpack(h2, h3);
            plo[kt2][sl]     = bpack(l0, l1);
            plo[kt2][sl + 1] = bpack(l2, l3);
        }

        if (kt < 15) { CP_WAIT(1); } else { CP_WAIT(0); }   // V(kt) landed
        __syncthreads();

        // ---- O += Phi*Vhi + Plo*Vhi + Phi*Vlo ----
#pragma unroll
        for (int np = 0; np < 4; np++) {
#pragma unroll
            for (int kt2 = 0; kt2 < 4; kt2++) {
                const uint32_t off = SMEM_SWZ((np * 16 + rowB) * 128 + kt2 * 32 + colB);
                uint32_t bvh[4], bvl[4];
                LDSM_X4(bvh, t32 + 32768 + off);
                LDSM_X4(bvl, t32 + 40960 + off);
                mma_bf16(oa[2 * np],     phi[kt2], bvh[0], bvh[1]);
                mma_bf16(oa[2 * np],     plo[kt2], bvh[0], bvh[1]);
                mma_bf16(oa[2 * np],     phi[kt2], bvl[0], bvl[1]);
                mma_bf16(oa[2 * np + 1], phi[kt2], bvh[2], bvh[3]);
                mma_bf16(oa[2 * np + 1], plo[kt2], bvh[2], bvh[3]);
                mma_bf16(oa[2 * np + 1], phi[kt2], bvl[2], bvl[3]);
            }
        }
    }

    // ---- finalize row sums (linear -> single quad reduction) ----
    lsum0 += __shfl_xor_sync(0xffffffffu, lsum0, 1);
    lsum0 += __shfl_xor_sync(0xffffffffu, lsum0, 2);
    lsum1 += __shfl_xor_sync(0xffffffffu, lsum1, 1);
    lsum1 += __shfl_xor_sync(0xffffffffu, lsum1, 2);
    const float inv0 = 1.0f / lsum0;
    const float inv1 = 1.0f / lsum1;

    __syncthreads();   // all tile reads done before As overwrites K buf0

    // stage normalized O into As[s_local][d] (stride 65)
    {
        const int r0 = w * 16 + (lane >> 2);
        const int r1 = r0 + 8;
#pragma unroll
        for (int nt = 0; nt < 8; nt++) {
            const int d0 = nt * 8 + (lane & 3) * 2;
            As[r0 * 65 + d0]     = oa[nt][0] * inv0;
            As[r0 * 65 + d0 + 1] = oa[nt][1] * inv0;
            As[r1 * 65 + d0]     = oa[nt][2] * inv1;
            As[r1 * 65 + d0 + 1] = oa[nt][3] * inv1;
        }
    }
    __syncthreads();

    // out[bh][lin] = a[s = lin&1023][d = lin>>10] + queries_in[bh][lin]
    const float* qin = queries_in + base;
    float* op = out + base;
#pragma unroll
    for (int t = 0; t < 32; t++) {
        const int idx = tid + t * 128;       // 0..4095
        const int d  = idx >> 6;
        const int sl = idx & 63;
        const int lin = d * 1024 + qbase + sl;
        op[lin] = As[sl * 65 + d] + qin[lin];
    }
}

// ---------------------------------------------------------------------------
// Launch: inputs in metadata order:
//  0 queries, 1 keys, 2 values, 3 Wq_w, 4 Wq_b, 5 Wk_w, 6 Wk_b, 7 Wv_w, 8 Wv_b
// ---------------------------------------------------------------------------
extern "C" void kernel_launch(void* const* d_in, const int* in_sizes, int n_in,
                              void* d_out, int out_size)
{
    const float* q  = (const float*)d_in[0];
    const float* k  = (const float*)d_in[1];
    const float* v  = (const float*)d_in[2];
    const float* Wq = (const float*)d_in[3];
    const float* bq = (const float*)d_in[4];
    const float* Wk = (const float*)d_in[5];
    const float* bk = (const float*)d_in[6];
    const float* Wv = (const float*)d_in[7];
    const float* bv = (const float*)d_in[8];
    float* out = (float*)d_out;

    proj_kernel<<<dim3(512, 3), 256>>>(q, k, v, Wq, bq, Wk, bk, Wv, bv);
    attn_kernel<<<dim3(16, 64), 128>>>(q, out);
}

// round 10
// speedup vs baseline: 10.2701x; 1.2810x over previous
#include <cuda_runtime.h>
#include <cuda_fp16.h>
#include <cstdint>

// Problem constants: B=8, H=8, S=1024, D=64
#define BH      64
#define SEQ     1024
#define HD      64
#define NROWS   (BH * SEQ)

typedef unsigned long long u64;

// ---------------------------------------------------------------------------
// Scratch (allocation-free rule: __device__ globals)
// q/k: [bh][s][d] fp16 hi/lo split.   v: TRANSPOSED [bh][d][s] fp16 (single).
// ---------------------------------------------------------------------------
__device__ __half g_qhi[NROWS * HD];
__device__ __half g_qlo[NROWS * HD];
__device__ __half g_khi[NROWS * HD];
__device__ __half g_klo[NROWS * HD];
__device__ __half g_vhi[NROWS * HD];

// ---- packed fp32x2 helpers (FFMA2, full fp32) -----------------------------
__device__ __forceinline__ u64 pack2(float x) {
    u64 r; asm("mov.b64 %0, {%1, %1};" : "=l"(r) : "f"(x)); return r;
}
__device__ __forceinline__ u64 pack2f(float lo, float hi) {
    u64 r; asm("mov.b64 %0, {%1, %2};" : "=l"(r) : "f"(lo), "f"(hi)); return r;
}
__device__ __forceinline__ float2 unpk(u64 v) {
    float2 f; asm("mov.b64 {%0, %1}, %2;" : "=f"(f.x), "=f"(f.y) : "l"(v)); return f;
}
__device__ __forceinline__ void fma2(u64& d, u64 a, u64 b) {
    asm("fma.rn.f32x2 %0, %1, %2, %0;" : "+l"(d) : "l"(a), "l"(b));
}

__device__ __forceinline__ uint32_t smem_to_u32(const void* p) {
    uint32_t a;
    asm("{ .reg .u64 t; cvta.to.shared.u64 t, %1; cvt.u32.u64 %0, t; }"
        : "=r"(a) : "l"(p));
    return a;
}

// XOR swizzle for 128B rows: byte_off ^ ((byte_off>>3)&0x70)
#define SMEM_SWZ(off) ((uint32_t)(off) ^ (((uint32_t)(off) >> 3) & 0x70))

// ---- cp.async (LDGSTS, sm_80+ base ISA) -----------------------------------
#define CP_ASYNC16(saddr, gptr) \
    asm volatile("cp.async.cg.shared.global [%0], [%1], 16;" \
        :: "r"((uint32_t)(saddr)), "l"(gptr) : "memory")
#define CP_COMMIT() asm volatile("cp.async.commit_group;" ::: "memory")
#define CP_WAIT(N)  asm volatile("cp.async.wait_group %0;" :: "n"(N) : "memory")

// ldmatrix x4 (non-transposed, b16)
#define LDSM_X4(r, addr) \
    asm volatile("ldmatrix.sync.aligned.m8n8.x4.shared.b16 {%0,%1,%2,%3}, [%4];" \
        : "=r"((r)[0]), "=r"((r)[1]), "=r"((r)[2]), "=r"((r)[3]) : "r"(addr))

// mma m16n8k16 fp16 in, fp32 accum; C==D accumulate
__device__ __forceinline__ void mma_f16(float c[4], const uint32_t a[4],
                                        uint32_t b0, uint32_t b1) {
    asm volatile(
        "mma.sync.aligned.m16n8k16.row.col.f32.f16.f16.f32 "
        "{%0,%1,%2,%3}, {%4,%5,%6,%7}, {%8,%9}, {%0,%1,%2,%3};"
        : "+f"(c[0]), "+f"(c[1]), "+f"(c[2]), "+f"(c[3])
        : "r"(a[0]), "r"(a[1]), "r"(a[2]), "r"(a[3]), "r"(b0), "r"(b1));
}

__device__ __forceinline__ void hsplit(float x, __half& h, __half& l) {
    h = __float2half_rn(x);
    l = __float2half_rn(x - __half2float(h));
}
__device__ __forceinline__ uint32_t hpack(__half lo, __half hi) {
    __half2 t; t.x = lo; t.y = hi;
    return *(uint32_t*)&t;
}

// async K tile (hi+lo, 64 keys x 64 d, 128B rows, swizzled) -> one group
__device__ __forceinline__ void cp_tile_K(uint32_t dsthi, uint32_t dstlo,
                                          const uint4* kh, const uint4* kl,
                                          int tid) {
#pragma unroll
    for (int c = tid; c < 512; c += 128) {
        const uint32_t sw = SMEM_SWZ(c * 16);
        CP_ASYNC16(dsthi + sw, kh + c);
        CP_ASYNC16(dstlo + sw, kl + c);
    }
    CP_COMMIT();
}
// async V tile (hi only, 64 d-rows x 64 keys from [d][s] gmem) -> one group
__device__ __forceinline__ void cp_tile_V(uint32_t dsthi,
                                          const __half* vh, int tid) {
#pragma unroll
    for (int c = tid; c < 512; c += 128) {
        const int row = c >> 3, cb = c & 7;
        const uint32_t sw = SMEM_SWZ(c * 16);
        CP_ASYNC16(dsthi + sw, (const uint4*)(vh + (size_t)row * SEQ) + cb);
    }
    CP_COMMIT();
}

// ---------------------------------------------------------------------------
// Fused projections (fp32 FFMA2 compute, fp16 outputs).
// grid (512, 3): y = q/k/v. 128 rows x 64 outputs per block, 256 threads.
// q: scaled by 1/8 (softmax scale folded), hi/lo. k: hi/lo.
// v: single fp16, stored transposed [bh][d][s].
// ---------------------------------------------------------------------------
__global__ __launch_bounds__(256) void proj_kernel(
    const float* __restrict__ Xq, const float* __restrict__ Xk,
    const float* __restrict__ Xv,
    const float* __restrict__ Wq, const float* __restrict__ bq,
    const float* __restrict__ Wk, const float* __restrict__ bk,
    const float* __restrict__ Wv, const float* __restrict__ bv)
{
    const int which = blockIdx.y;
    const float* __restrict__ X    = (which == 0) ? Xq : (which == 1) ? Xk : Xv;
    const float* __restrict__ W    = (which == 0) ? Wq : (which == 1) ? Wk : Wv;
    const float* __restrict__ bias = (which == 0) ? bq : (which == 1) ? bk : bv;

    __shared__ __align__(16) float Xs[128 * 64];
    __shared__ __align__(16) float Ws[64 * 64];   // transposed Wt[d][e]

    const int tid = threadIdx.x;
    const size_t rowBase = (size_t)blockIdx.x * 128;

    {
        const float4* xs = (const float4*)(X + rowBase * HD);
        float4* Xd = (float4*)Xs;
#pragma unroll
        for (int i = 0; i < 8; i++) Xd[tid + i * 256] = xs[tid + i * 256];
    }
#pragma unroll
    for (int i = 0; i < 4; i++) {
        const int idx = tid + i * 256;
        const int e  = idx & 63;
        const int d4 = idx >> 6;
        const float4 w = *(const float4*)&W[e * 64 + d4 * 4];
        Ws[(d4 * 4 + 0) * 64 + e] = w.x;
        Ws[(d4 * 4 + 1) * 64 + e] = w.y;
        Ws[(d4 * 4 + 2) * 64 + e] = w.z;
        Ws[(d4 * 4 + 3) * 64 + e] = w.w;
    }
    __syncthreads();

    const int tr = tid >> 4;
    const int tc = tid & 15;

    u64 acc[8][2];
#pragma unroll
    for (int i = 0; i < 8; i++) { acc[i][0] = 0ull; acc[i][1] = 0ull; }

#pragma unroll 4
    for (int k = 0; k < 64; k += 4) {
        u64 b[4][2];
#pragma unroll
        for (int kk = 0; kk < 4; kk++) {
            const float4 bb = *(const float4*)&Ws[(k + kk) * 64 + tc * 4];
            b[kk][0] = pack2f(bb.x, bb.y);
            b[kk][1] = pack2f(bb.z, bb.w);
        }
#pragma unroll
        for (int i = 0; i < 8; i++) {
            const float4 a = *(const float4*)&Xs[(tr * 8 + i) * 64 + k];
            u64 ap;
            ap = pack2(a.x); fma2(acc[i][0], ap, b[0][0]); fma2(acc[i][1], ap, b[0][1]);
            ap = pack2(a.y); fma2(acc[i][0], ap, b[1][0]); fma2(acc[i][1], ap, b[1][1]);
            ap = pack2(a.z); fma2(acc[i][0], ap, b[2][0]); fma2(acc[i][1], ap, b[2][1]);
            ap = pack2(a.w); fma2(acc[i][0], ap, b[3][0]); fma2(acc[i][1], ap, b[3][1]);
        }
    }

    const float4 bv4 = *(const float4*)&bias[tc * 4];
    float r[8][4];
#pragma unroll
    for (int i = 0; i < 8; i++) {
        const float2 c01 = unpk(acc[i][0]);
        const float2 c23 = unpk(acc[i][1]);
        r[i][0] = fmaxf(c01.x + bv4.x, 0.0f);
        r[i][1] = fmaxf(c01.y + bv4.y, 0.0f);
        r[i][2] = fmaxf(c23.x + bv4.z, 0.0f);
        r[i][3] = fmaxf(c23.y + bv4.w, 0.0f);
    }
    if (which == 0) {   // fold 1/sqrt(64) into q
#pragma unroll
        for (int i = 0; i < 8; i++)
#pragma unroll
            for (int j = 0; j < 4; j++) r[i][j] *= 0.125f;
    }

    if (which == 2) {
        // V transposed, single fp16: g_vhi[(bh*64 + d)*1024 + s]
        const int bh = (int)(rowBase >> 10);
        const int s0 = (int)(rowBase & 1023);
#pragma unroll
        for (int j = 0; j < 4; j++) {
            __half h8[8];
#pragma unroll
            for (int i = 0; i < 8; i++) h8[i] = __float2half_rn(r[i][j]);
            const size_t off = ((size_t)bh * 64 + tc * 4 + j) * 1024 + s0 + tr * 8;
            *(uint4*)&g_vhi[off] = *(uint4*)h8;
        }
    } else {
        __half* Yh = (which == 0) ? g_qhi : g_khi;
        __half* Yl = (which == 0) ? g_qlo : g_klo;
#pragma unroll
        for (int i = 0; i < 8; i++) {
            __half h4[4], l4[4];
#pragma unroll
            for (int j = 0; j < 4; j++) hsplit(r[i][j], h4[j], l4[j]);
            const size_t off = (rowBase + tr * 8 + i) * HD + tc * 4;
            *(uint2*)&Yh[off] = *(uint2*)h4;
            *(uint2*)&Yl[off] = *(uint2*)l4;
        }
    }
}

// ---------------------------------------------------------------------------
// mma.sync fp16 flash attention, fully double-buffered cp.async pipeline.
// QK: 3-term fp16 split (exp argument is precision-critical).
// PV: single-term fp16 (P,V quantization ~2^-11; lsum over quantized P makes
//     softmax self-normalizing for common-mode error).
// One CTA = (bh, 64-query tile). 4 warps x 16 q-rows. Grid (16, 64).
//
// SMEM (48KB static; XOR-swizzled 128B rows):
//   [    0: 8192) Khi buf0   [ 8192:16384) Klo buf0
//   [16384:24576) Khi buf1   [24576:32768) Klo buf1   (also Q staging)
//   [32768:40960) Vhi buf0   [40960:49152) Vhi buf1
//   As (64x65 f32 epilogue) overlays buf0 region.
//
// Pipeline: prologue issues K0,V0 (groups), stages+extracts Q, issues K1,V1.
// Iter kt: wait_group 2 (K(kt),V(kt) landed) ; sync ; QK ; exp ; PV ; sync ;
//          issue K(kt+2),V(kt+2) into buf[kt&1].
//
// Fragment layouts (PTX mma m16n8k16 row.col), g = lane>>2, q = lane&3:
//   A: a0:(r=g,k=2q+{0,1}) a1:(r=g+8,...) a2:(r=g,k=2q+{8,9}) a3:(r=g+8,...)
//   B: b0:(k=2q+{0,1},n=g) b1:(k=2q+{8,9},n=g)
//   C: c0,c1:(r=g,n=2q,2q+1) c2,c3:(r=g+8,same)
// ---------------------------------------------------------------------------
__global__ __launch_bounds__(128) void attn_kernel(
    const float* __restrict__ queries_in, float* __restrict__ out)
{
    __shared__ __align__(128) char tiles[49152];

    const int tid  = threadIdx.x;
    const int lane = tid & 31;
    const int w    = tid >> 5;
    const int bh = blockIdx.y;
    const int qbase = blockIdx.x * 64;
    const size_t base = (size_t)bh * (SEQ * HD);
    const size_t vbase = (size_t)bh * (HD * SEQ);

    const uint32_t t32 = smem_to_u32(tiles);
    float* As = (float*)tiles;              // epilogue buffer overlays buf0

    // ldmatrix lane->address decomposition
    const int rowA = (lane & 7) + ((lane & 8)  ? 8 : 0);
    const int colA = (lane & 16) ? 16 : 0;
    const int rowB = (lane & 7) + ((lane & 16) ? 8 : 0);
    const int colB = (lane & 8)  ? 16 : 0;

    // ---- prefetch K(0) (G0), V(0) (G1) ----
    cp_tile_K(t32, t32 + 8192,
              (const uint4*)(g_khi + base), (const uint4*)(g_klo + base), tid);
    cp_tile_V(t32 + 32768, g_vhi + vbase, tid);

    // ---- stage Q tile into K buf1 region (normal stores), swizzled ----
    {
        const uint4* qh = (const uint4*)(g_qhi + base + (size_t)qbase * HD);
        const uint4* ql = (const uint4*)(g_qlo + base + (size_t)qbase * HD);
#pragma unroll
        for (int c = tid; c < 512; c += 128) {
            const uint32_t sw = SMEM_SWZ(c * 16);
            *(uint4*)(tiles + 16384 + sw) = qh[c];
            *(uint4*)(tiles + 24576 + sw) = ql[c];
        }
    }
    __syncthreads();

    // ---- Q fragments (persist in registers) ----
    uint32_t qh[4][4], ql[4][4];
#pragma unroll
    for (int kt2 = 0; kt2 < 4; kt2++) {
        const uint32_t off = SMEM_SWZ((w * 16 + rowA) * 128 + kt2 * 32 + colA);
        LDSM_X4(qh[kt2], t32 + 16384 + off);
        LDSM_X4(ql[kt2], t32 + 24576 + off);
    }
    __syncthreads();   // Q reads done -> buf1 free for K(1)

    // ---- prefetch K(1) (G2), V(1) (G3) ----
    cp_tile_K(t32 + 16384, t32 + 24576,
              (const uint4*)(g_khi + base + 64 * HD),
              (const uint4*)(g_klo + base + 64 * HD), tid);
    cp_tile_V(t32 + 40960, g_vhi + vbase + 64, tid);

    float oa[8][4];
#pragma unroll
    for (int i = 0; i < 8; i++)
#pragma unroll
        for (int j = 0; j < 4; j++) oa[i][j] = 0.0f;
    float lsum0 = 0.0f, lsum1 = 0.0f;

    for (int kt = 0; kt < 16; kt++) {
        const uint32_t kbhi = t32 + ((kt & 1) ? 16384u : 0u);
        const uint32_t kblo = kbhi + 8192;
        const uint32_t vbuf = t32 + 32768 + ((kt & 1) ? 8192u : 0u);

        if (kt < 14) { CP_WAIT(2); } else { CP_WAIT(0); }   // K(kt),V(kt) landed
        __syncthreads();

        // ---- S = Qhi*Khi + Qlo*Khi + Qhi*Klo ----
        float sa[8][4];
#pragma unroll
        for (int i = 0; i < 8; i++)
#pragma unroll
            for (int j = 0; j < 4; j++) sa[i][j] = 0.0f;

#pragma unroll
        for (int np = 0; np < 4; np++) {
#pragma unroll
            for (int kt2 = 0; kt2 < 4; kt2++) {
                const uint32_t off = SMEM_SWZ((np * 16 + rowB) * 128 + kt2 * 32 + colB);
                uint32_t bkh[4], bkl[4];
                LDSM_X4(bkh, kbhi + off);
                LDSM_X4(bkl, kblo + off);
                mma_f16(sa[2 * np],     qh[kt2], bkh[0], bkh[1]);
                mma_f16(sa[2 * np],     ql[kt2], bkh[0], bkh[1]);
                mma_f16(sa[2 * np],     qh[kt2], bkl[0], bkl[1]);
                mma_f16(sa[2 * np + 1], qh[kt2], bkh[2], bkh[3]);
                mma_f16(sa[2 * np + 1], ql[kt2], bkh[2], bkh[3]);
                mma_f16(sa[2 * np + 1], qh[kt2], bkl[2], bkl[3]);
            }
        }

        // ---- P = exp(S) -> fp16; lsum over QUANTIZED values ----
        uint32_t phi[4][4];
#pragma unroll
        for (int nt = 0; nt < 8; nt++) {
            const __half h0 = __float2half_rn(__expf(sa[nt][0]));
            const __half h1 = __float2half_rn(__expf(sa[nt][1]));
            const __half h2 = __float2half_rn(__expf(sa[nt][2]));
            const __half h3 = __float2half_rn(__expf(sa[nt][3]));
            lsum0 += __half2float(h0) + __half2float(h1);
            lsum1 += __half2float(h2) + __half2float(h3);
            const int kt2 = nt >> 1, sl = (nt & 1) * 2;
            phi[kt2][sl]     = hpack(h0, h1);
            phi[kt2][sl + 1] = hpack(h2, h3);
        }

        // ---- O += Phi * Vhi (single term) ----
#pragma unroll
        for (int np = 0; np < 4; np++) {
#pragma unroll
            for (int kt2 = 0; kt2 < 4; kt2++) {
                const uint32_t off = SMEM_SWZ((np * 16 + rowB) * 128 + kt2 * 32 + colB);
                uint32_t bvh[4];
                LDSM_X4(bvh, vbuf + off);
                mma_f16(oa[2 * np],     phi[kt2], bvh[0], bvh[1]);
                mma_f16(oa[2 * np + 1], phi[kt2], bvh[2], bvh[3]);
            }
        }

        __syncthreads();   // all reads of buf[kt&1] done
        if (kt < 14) {     // prefetch kt+2 into buf[kt&1]
            cp_tile_K(kbhi, kblo,
                      (const uint4*)(g_khi + base + (size_t)(kt + 2) * 64 * HD),
                      (const uint4*)(g_klo + base + (size_t)(kt + 2) * 64 * HD), tid);
            cp_tile_V(vbuf, g_vhi + vbase + (kt + 2) * 64, tid);
        }
    }

    // ---- finalize row sums (linear -> single quad reduction) ----
    lsum0 += __shfl_xor_sync(0xffffffffu, lsum0, 1);
    lsum0 += __shfl_xor_sync(0xffffffffu, lsum0, 2);
    lsum1 += __shfl_xor_sync(0xffffffffu, lsum1, 1);
    lsum1 += __shfl_xor_sync(0xffffffffu, lsum1, 2);
    const float inv0 = 1.0f / lsum0;
    const float inv1 = 1.0f / lsum1;

    // stage normalized O into As[s_local][d] (stride 65); As overlays buf0,
    // last read at kt=14; kt=15 used buf1 and the loop-end sync has passed.
    {
        const int r0 = w * 16 + (lane >> 2);
        const int r1 = r0 + 8;
#pragma unroll
        for (int nt = 0; nt < 8; nt++) {
            const int d0 = nt * 8 + (lane & 3) * 2;
            As[r0 * 65 + d0]     = oa[nt][0] * inv0;
            As[r0 * 65 + d0 + 1] = oa[nt][1] * inv0;
            As[r1 * 65 + d0]     = oa[nt][2] * inv1;
            As[r1 * 65 + d0 + 1] = oa[nt][3] * inv1;
        }
    }
    __syncthreads();

    // out[bh][lin] = a[s = lin&1023][d = lin>>10] + queries_in[bh][lin]
    const float* qin = queries_in + base;
    float* op = out + base;
#pragma unroll
    for (int t = 0; t < 32; t++) {
        const int idx = tid + t * 128;       // 0..4095
        const int d  = idx >> 6;
        const int sl = idx & 63;
        const int lin = d * 1024 + qbase + sl;
        op[lin] = As[sl * 65 + d] + qin[lin];
    }
}

// ---------------------------------------------------------------------------
// Launch: inputs in metadata order:
//  0 queries, 1 keys, 2 values, 3 Wq_w, 4 Wq_b, 5 Wk_w, 6 Wk_b, 7 Wv_w, 8 Wv_b
// ---------------------------------------------------------------------------
extern "C" void kernel_launch(void* const* d_in, const int* in_sizes, int n_in,
                              void* d_out, int out_size)
{
    const float* q  = (const float*)d_in[0];
    const float* k  = (const float*)d_in[1];
    const float* v  = (const float*)d_in[2];
    const float* Wq = (const float*)d_in[3];
    const float* bq = (const float*)d_in[4];
    const float* Wk = (const float*)d_in[5];
    const float* bk = (const float*)d_in[6];
    const float* Wv = (const float*)d_in[7];
    const float* bv = (const float*)d_in[8];
    float* out = (float*)d_out;

    proj_kernel<<<dim3(512, 3), 256>>>(q, k, v, Wq, bq, Wk, bk, Wv, bv);
    attn_kernel<<<dim3(16, 64), 128>>>(q, out);
}

// round 13
// speedup vs baseline: 11.9818x; 1.1667x over previous
#include <cuda_runtime.h>
#include <cuda_fp16.h>
#include <cstdint>

// Problem constants: B=8, H=8, S=1024, D=64
#define BH      64
#define SEQ     1024
#define HD      64
#define NROWS   (BH * SEQ)

typedef unsigned long long u64;

// ---------------------------------------------------------------------------
// Scratch (allocation-free rule: __device__ globals)
// q: [bh][s][d] fp16 hi/lo (exact split).  k: [bh][s][d] fp16 single.
// v: TRANSPOSED [bh][d][s] fp16 single.
// ---------------------------------------------------------------------------
__device__ __half g_qhi[NROWS * HD];
__device__ __half g_qlo[NROWS * HD];
__device__ __half g_khi[NROWS * HD];
__device__ __half g_vhi[NROWS * HD];

// ---- packed fp32x2 helpers (FFMA2, full fp32) -----------------------------
__device__ __forceinline__ u64 pack2(float x) {
    u64 r; asm("mov.b64 %0, {%1, %1};" : "=l"(r) : "f"(x)); return r;
}
__device__ __forceinline__ u64 pack2f(float lo, float hi) {
    u64 r; asm("mov.b64 %0, {%1, %2};" : "=l"(r) : "f"(lo), "f"(hi)); return r;
}
__device__ __forceinline__ float2 unpk(u64 v) {
    float2 f; asm("mov.b64 {%0, %1}, %2;" : "=f"(f.x), "=f"(f.y) : "l"(v)); return f;
}
__device__ __forceinline__ void fma2(u64& d, u64 a, u64 b) {
    asm("fma.rn.f32x2 %0, %1, %2, %0;" : "+l"(d) : "l"(a), "l"(b));
}

__device__ __forceinline__ uint32_t smem_to_u32(const void* p) {
    uint32_t a;
    asm("{ .reg .u64 t; cvta.to.shared.u64 t, %1; cvt.u32.u64 %0, t; }"
        : "=r"(a) : "l"(p));
    return a;
}

// XOR swizzle for 128B rows: byte_off ^ ((byte_off>>3)&0x70)
#define SMEM_SWZ(off) ((uint32_t)(off) ^ (((uint32_t)(off) >> 3) & 0x70))

// ---- cp.async (LDGSTS, sm_80+ base ISA) -----------------------------------
#define CP_ASYNC16(saddr, gptr) \
    asm volatile("cp.async.cg.shared.global [%0], [%1], 16;" \
        :: "r"((uint32_t)(saddr)), "l"(gptr) : "memory")
#define CP_COMMIT() asm volatile("cp.async.commit_group;" ::: "memory")
#define CP_WAIT(N)  asm volatile("cp.async.wait_group %0;" :: "n"(N) : "memory")

// ldmatrix x4 (non-transposed, b16)
#define LDSM_X4(r, addr) \
    asm volatile("ldmatrix.sync.aligned.m8n8.x4.shared.b16 {%0,%1,%2,%3}, [%4];" \
        : "=r"((r)[0]), "=r"((r)[1]), "=r"((r)[2]), "=r"((r)[3]) : "r"(addr))

// mma m16n8k16 fp16 in, fp32 accum; C==D accumulate
__device__ __forceinline__ void mma_f16(float c[4], const uint32_t a[4],
                                        uint32_t b0, uint32_t b1) {
    asm volatile(
        "mma.sync.aligned.m16n8k16.row.col.f32.f16.f16.f32 "
        "{%0,%1,%2,%3}, {%4,%5,%6,%7}, {%8,%9}, {%0,%1,%2,%3};"
        : "+f"(c[0]), "+f"(c[1]), "+f"(c[2]), "+f"(c[3])
        : "r"(a[0]), "r"(a[1]), "r"(a[2]), "r"(a[3]), "r"(b0), "r"(b1));
}

__device__ __forceinline__ void hsplit(float x, __half& h, __half& l) {
    h = __float2half_rn(x);
    l = __float2half_rn(x - __half2float(h));
}
__device__ __forceinline__ uint32_t hpack(__half lo, __half hi) {
    __half2 t; t.x = lo; t.y = hi;
    return *(uint32_t*)&t;
}

// async {K,V} tile pair -> ONE commit group.
// K: 64 keys x 64 d contiguous rows (128B). V: 64 d-rows x 64 keys, [d][s] gmem.
__device__ __forceinline__ void cp_tile_KV(uint32_t dstK, uint32_t dstV,
                                           const uint4* kh, const __half* vh,
                                           int tid) {
#pragma unroll
    for (int c = tid; c < 512; c += 128) {
        const uint32_t sw = SMEM_SWZ(c * 16);
        CP_ASYNC16(dstK + sw, kh + c);
        const int row = c >> 3, cb = c & 7;
        CP_ASYNC16(dstV + sw, (const uint4*)(vh + (size_t)row * SEQ) + cb);
    }
    CP_COMMIT();
}

// ---------------------------------------------------------------------------
// Fused projections (fp32 FFMA2 compute, fp16 outputs).
// grid (512, 3): y = q/k/v. 128 rows x 64 outputs per block, 256 threads.
// q: scaled by 1/8 (softmax scale folded), hi/lo exact split.
// k: single fp16. v: single fp16, stored transposed [bh][d][s].
// ---------------------------------------------------------------------------
__global__ __launch_bounds__(256) void proj_kernel(
    const float* __restrict__ Xq, const float* __restrict__ Xk,
    const float* __restrict__ Xv,
    const float* __restrict__ Wq, const float* __restrict__ bq,
    const float* __restrict__ Wk, const float* __restrict__ bk,
    const float* __restrict__ Wv, const float* __restrict__ bv)
{
    const int which = blockIdx.y;
    const float* __restrict__ X    = (which == 0) ? Xq : (which == 1) ? Xk : Xv;
    const float* __restrict__ W    = (which == 0) ? Wq : (which == 1) ? Wk : Wv;
    const float* __restrict__ bias = (which == 0) ? bq : (which == 1) ? bk : bv;

    __shared__ __align__(16) float Xs[128 * 64];
    __shared__ __align__(16) float Ws[64 * 64];   // transposed Wt[d][e]

    const int tid = threadIdx.x;
    const size_t rowBase = (size_t)blockIdx.x * 128;

    {
        const float4* xs = (const float4*)(X + rowBase * HD);
        float4* Xd = (float4*)Xs;
#pragma unroll
        for (int i = 0; i < 8; i++) Xd[tid + i * 256] = xs[tid + i * 256];
    }
#pragma unroll
    for (int i = 0; i < 4; i++) {
        const int idx = tid + i * 256;
        const int e  = idx & 63;
        const int d4 = idx >> 6;
        const float4 w = *(const float4*)&W[e * 64 + d4 * 4];
        Ws[(d4 * 4 + 0) * 64 + e] = w.x;
        Ws[(d4 * 4 + 1) * 64 + e] = w.y;
        Ws[(d4 * 4 + 2) * 64 + e] = w.z;
        Ws[(d4 * 4 + 3) * 64 + e] = w.w;
    }
    __syncthreads();

    const int tr = tid >> 4;
    const int tc = tid & 15;

    u64 acc[8][2];
#pragma unroll
    for (int i = 0; i < 8; i++) { acc[i][0] = 0ull; acc[i][1] = 0ull; }

#pragma unroll 4
    for (int k = 0; k < 64; k += 4) {
        u64 b[4][2];
#pragma unroll
        for (int kk = 0; kk < 4; kk++) {
            const float4 bb = *(const float4*)&Ws[(k + kk) * 64 + tc * 4];
            b[kk][0] = pack2f(bb.x, bb.y);
            b[kk][1] = pack2f(bb.z, bb.w);
        }
#pragma unroll
        for (int i = 0; i < 8; i++) {
            const float4 a = *(const float4*)&Xs[(tr * 8 + i) * 64 + k];
            u64 ap;
            ap = pack2(a.x); fma2(acc[i][0], ap, b[0][0]); fma2(acc[i][1], ap, b[0][1]);
            ap = pack2(a.y); fma2(acc[i][0], ap, b[1][0]); fma2(acc[i][1], ap, b[1][1]);
            ap = pack2(a.z); fma2(acc[i][0], ap, b[2][0]); fma2(acc[i][1], ap, b[2][1]);
            ap = pack2(a.w); fma2(acc[i][0], ap, b[3][0]); fma2(acc[i][1], ap, b[3][1]);
        }
    }

    const float4 bv4 = *(const float4*)&bias[tc * 4];
    float r[8][4];
#pragma unroll
    for (int i = 0; i < 8; i++) {
        const float2 c01 = unpk(acc[i][0]);
        const float2 c23 = unpk(acc[i][1]);
        r[i][0] = fmaxf(c01.x + bv4.x, 0.0f);
        r[i][1] = fmaxf(c01.y + bv4.y, 0.0f);
        r[i][2] = fmaxf(c23.x + bv4.z, 0.0f);
        r[i][3] = fmaxf(c23.y + bv4.w, 0.0f);
    }
    if (which == 0) {   // fold 1/sqrt(64) into q
#pragma unroll
        for (int i = 0; i < 8; i++)
#pragma unroll
            for (int j = 0; j < 4; j++) r[i][j] *= 0.125f;
    }

    if (which == 2) {
        // V transposed, single fp16: g_vhi[(bh*64 + d)*1024 + s]
        const int bh = (int)(rowBase >> 10);
        const int s0 = (int)(rowBase & 1023);
#pragma unroll
        for (int j = 0; j < 4; j++) {
            __half h8[8];
#pragma unroll
            for (int i = 0; i < 8; i++) h8[i] = __float2half_rn(r[i][j]);
            const size_t off = ((size_t)bh * 64 + tc * 4 + j) * 1024 + s0 + tr * 8;
            *(uint4*)&g_vhi[off] = *(uint4*)h8;
        }
    } else if (which == 1) {
        // K single fp16
#pragma unroll
        for (int i = 0; i < 8; i++) {
            __half h4[4];
#pragma unroll
            for (int j = 0; j < 4; j++) h4[j] = __float2half_rn(r[i][j]);
            const size_t off = (rowBase + tr * 8 + i) * HD + tc * 4;
            *(uint2*)&g_khi[off] = *(uint2*)h4;
        }
    } else {
        // Q exact hi/lo split
#pragma unroll
        for (int i = 0; i < 8; i++) {
            __half h4[4], l4[4];
#pragma unroll
            for (int j = 0; j < 4; j++) hsplit(r[i][j], h4[j], l4[j]);
            const size_t off = (rowBase + tr * 8 + i) * HD + tc * 4;
            *(uint2*)&g_qhi[off] = *(uint2*)h4;
            *(uint2*)&g_qlo[off] = *(uint2*)l4;
        }
    }
}

// ---------------------------------------------------------------------------
// mma.sync fp16 flash attention, double-buffered cp.async pipeline.
// QK: 2-term — S = (Qhi + Qlo)*Khi. Q is EXACT (hi+lo fp32 decomposition);
//     only K's fp16 quantization remains (~2^-11, measured ~5e-6 output
//     impact for the analogous single-term PV).
// PV: single-term fp16 (lsum over quantized P self-normalizes common mode).
// One CTA = (bh, 64-query tile). 4 warps x 16 q-rows. Grid (16, 64).
//
// SMEM (32KB static; XOR-swizzled 128B rows):
//   [    0: 8192) Khi buf0   [ 8192:16384) Khi buf1 (Q-hi staging)
//   [16384:24576) Vhi buf0   [24576:32768) Vhi buf1 (Q-lo staging)
//   As (64x65 f32 epilogue, 16.6KB) overlays [0:16640).
//
// Pipeline (1 cp.async group per {K,V} tile pair):
//   prologue: G0={K0,V0} ; stage Q -> Kb1/Vb1 ; sync ; extract Q ; sync ;
//             G1={K1,V1}
//   iter kt:  wait_group(kt<15?1:0) -> G_kt landed ; sync ; QK ; exp ; PV ;
//             sync ; if kt<14: G_{kt+2} -> buf[kt&1]
//
// Fragment layouts (PTX mma m16n8k16 row.col), g = lane>>2, q = lane&3:
//   A: a0:(r=g,k=2q+{0,1}) a1:(r=g+8,...) a2:(r=g,k=2q+{8,9}) a3:(r=g+8,...)
//   B: b0:(k=2q+{0,1},n=g) b1:(k=2q+{8,9},n=g)
//   C: c0,c1:(r=g,n=2q,2q+1) c2,c3:(r=g+8,same)
// ---------------------------------------------------------------------------
__global__ __launch_bounds__(128) void attn_kernel(
    const float* __restrict__ queries_in, float* __restrict__ out)
{
    __shared__ __align__(128) char tiles[32768];

    const int tid  = threadIdx.x;
    const int lane = tid & 31;
    const int w    = tid >> 5;
    const int bh = blockIdx.y;
    const int qbase = blockIdx.x * 64;
    const size_t base = (size_t)bh * (SEQ * HD);
    const size_t vbase = (size_t)bh * (HD * SEQ);

    const uint32_t t32 = smem_to_u32(tiles);
    float* As = (float*)tiles;              // epilogue buffer overlays [0:16640)

    // ldmatrix lane->address decomposition
    const int rowA = (lane & 7) + ((lane & 8)  ? 8 : 0);
    const int colA = (lane & 16) ? 16 : 0;
    const int rowB = (lane & 7) + ((lane & 16) ? 8 : 0);
    const int colB = (lane & 8)  ? 16 : 0;

    // ---- G0 = {K0, V0} into buf0 ----
    cp_tile_KV(t32, t32 + 16384,
               (const uint4*)(g_khi + base), g_vhi + vbase, tid);

    // ---- stage Q: hi -> K buf1, lo -> V buf1 (regular stores, swizzled) ----
    {
        const uint4* qh = (const uint4*)(g_qhi + base + (size_t)qbase * HD);
        const uint4* ql = (const uint4*)(g_qlo + base + (size_t)qbase * HD);
#pragma unroll
        for (int c = tid; c < 512; c += 128) {
            const uint32_t sw = SMEM_SWZ(c * 16);
            *(uint4*)(tiles + 8192 + sw)  = qh[c];
            *(uint4*)(tiles + 24576 + sw) = ql[c];
        }
    }
    __syncthreads();

    // ---- Q fragments (persist in registers) ----
    uint32_t qh[4][4], ql[4][4];
#pragma unroll
    for (int kt2 = 0; kt2 < 4; kt2++) {
        const uint32_t off = SMEM_SWZ((w * 16 + rowA) * 128 + kt2 * 32 + colA);
        LDSM_X4(qh[kt2], t32 + 8192 + off);
        LDSM_X4(ql[kt2], t32 + 24576 + off);
    }
    __syncthreads();   // Q reads done -> buf1 regions free

    // ---- G1 = {K1, V1} into buf1 ----
    cp_tile_KV(t32 + 8192, t32 + 24576,
               (const uint4*)(g_khi + base + 64 * HD), g_vhi + vbase + 64, tid);

    float oa[8][4];
#pragma unroll
    for (int i = 0; i < 8; i++)
#pragma unroll
        for (int j = 0; j < 4; j++) oa[i][j] = 0.0f;
    float lsum0 = 0.0f, lsum1 = 0.0f;

    for (int kt = 0; kt < 16; kt++) {
        const uint32_t kbuf = t32 + ((kt & 1) ? 8192u : 0u);
        const uint32_t vbuf = t32 + 16384 + ((kt & 1) ? 8192u : 0u);

        if (kt < 15) { CP_WAIT(1); } else { CP_WAIT(0); }   // G_kt landed
        __syncthreads();

        // ---- S = (Qhi + Qlo) * Khi ----
        float sa[8][4];
#pragma unroll
        for (int i = 0; i < 8; i++)
#pragma unroll
            for (int j = 0; j < 4; j++) sa[i][j] = 0.0f;

#pragma unroll
        for (int np = 0; np < 4; np++) {
#pragma unroll
            for (int kt2 = 0; kt2 < 4; kt2++) {
                const uint32_t off = SMEM_SWZ((np * 16 + rowB) * 128 + kt2 * 32 + colB);
                uint32_t bkh[4];
                LDSM_X4(bkh, kbuf + off);
                mma_f16(sa[2 * np],     qh[kt2], bkh[0], bkh[1]);
                mma_f16(sa[2 * np],     ql[kt2], bkh[0], bkh[1]);
                mma_f16(sa[2 * np + 1], qh[kt2], bkh[2], bkh[3]);
                mma_f16(sa[2 * np + 1], ql[kt2], bkh[2], bkh[3]);
            }
        }

        // ---- P = exp(S) -> fp16; lsum over QUANTIZED values ----
        uint32_t phi[4][4];
#pragma unroll
        for (int nt = 0; nt < 8; nt++) {
            const __half h0 = __float2half_rn(__expf(sa[nt][0]));
            const __half h1 = __float2half_rn(__expf(sa[nt][1]));
            const __half h2 = __float2half_rn(__expf(sa[nt][2]));
            const __half h3 = __float2half_rn(__expf(sa[nt][3]));
            lsum0 += __half2float(h0) + __half2float(h1);
            lsum1 += __half2float(h2) + __half2float(h3);
            const int kt2 = nt >> 1, sl = (nt & 1) * 2;
            phi[kt2][sl]     = hpack(h0, h1);
            phi[kt2][sl + 1] = hpack(h2, h3);
        }

        // ---- O += Phi * Vhi ----
#pragma unroll
        for (int np = 0; np < 4; np++) {
#pragma unroll
            for (int kt2 = 0; kt2 < 4; kt2++) {
                const uint32_t off = SMEM_SWZ((np * 16 + rowB) * 128 + kt2 * 32 + colB);
                uint32_t bvh[4];
                LDSM_X4(bvh, vbuf + off);
                mma_f16(oa[2 * np],     phi[kt2], bvh[0], bvh[1]);
                mma_f16(oa[2 * np + 1], phi[kt2], bvh[2], bvh[3]);
            }
        }

        __syncthreads();   // all reads of buf[kt&1] done
        if (kt < 14) {     // G_{kt+2} into buf[kt&1]
            cp_tile_KV(kbuf, vbuf,
                       (const uint4*)(g_khi + base + (size_t)(kt + 2) * 64 * HD),
                       g_vhi + vbase + (kt + 2) * 64, tid);
        }
    }

    // ---- finalize row sums (linear -> single quad reduction) ----
    lsum0 += __shfl_xor_sync(0xffffffffu, lsum0, 1);
    lsum0 += __shfl_xor_sync(0xffffffffu, lsum0, 2);
    lsum1 += __shfl_xor_sync(0xffffffffu, lsum1, 1);
    lsum1 += __shfl_xor_sync(0xffffffffu, lsum1, 2);
    const float inv0 = 1.0f / lsum0;
    const float inv1 = 1.0f / lsum1;

    // stage normalized O into As[s_local][d] (stride 65); the loop-end
    // __syncthreads() of kt=15 ordered all tile reads before these writes.
    {
        const int r0 = w * 16 + (lane >> 2);
        const int r1 = r0 + 8;
#pragma unroll
        for (int nt = 0; nt < 8; nt++) {
            const int d0 = nt * 8 + (lane & 3) * 2;
            As[r0 * 65 + d0]     = oa[nt][0] * inv0;
            As[r0 * 65 + d0 + 1] = oa[nt][1] * inv0;
            As[r1 * 65 + d0]     = oa[nt][2] * inv1;
            As[r1 * 65 + d0 + 1] = oa[nt][3] * inv1;
        }
    }
    __syncthreads();

    // out[bh][lin] = a[s = lin&1023][d = lin>>10] + queries_in[bh][lin]
    const float* qin = queries_in + base;
    float* op = out + base;
#pragma unroll
    for (int t = 0; t < 32; t++) {
        const int idx = tid + t * 128;       // 0..4095
        const int d  = idx >> 6;
        const int sl = idx & 63;
        const int lin = d * 1024 + qbase + sl;
        op[lin] = As[sl * 65 + d] + qin[lin];
    }
}

// ---------------------------------------------------------------------------
// Launch: inputs in metadata order:
//  0 queries, 1 keys, 2 values, 3 Wq_w, 4 Wq_b, 5 Wk_w, 6 Wk_b, 7 Wv_w, 8 Wv_b
// ---------------------------------------------------------------------------
extern "C" void kernel_launch(void* const* d_in, const int* in_sizes, int n_in,
                              void* d_out, int out_size)
{
    const float* q  = (const float*)d_in[0];
    const float* k  = (const float*)d_in[1];
    const float* v  = (const float*)d_in[2];
    const float* Wq = (const float*)d_in[3];
    const float* bq = (const float*)d_in[4];
    const float* Wk = (const float*)d_in[5];
    const float* bk = (const float*)d_in[6];
    const float* Wv = (const float*)d_in[7];
    const float* bv = (const float*)d_in[8];
    float* out = (float*)d_out;

    proj_kernel<<<dim3(512, 3), 256>>>(q, k, v, Wq, bq, Wk, bk, Wv, bv);
    attn_kernel<<<dim3(16, 64), 128>>>(q, out);
}

// round 14
// speedup vs baseline: 13.5683x; 1.1324x over previous
#include <cuda_runtime.h>
#include <cuda_fp16.h>
#include <cstdint>

// Problem constants: B=8, H=8, S=1024, D=64
#define BH      64
#define SEQ     1024
#define HD      64
#define NROWS   (BH * SEQ)

typedef unsigned long long u64;

// ---------------------------------------------------------------------------
// Scratch (allocation-free rule: __device__ globals)
// q/k: [bh][s][d] fp16 single.   v: TRANSPOSED [bh][d][s] fp16 single.
// (q carries the folded 1/8 softmax scale)
// ---------------------------------------------------------------------------
__device__ __half g_qhi[NROWS * HD];
__device__ __half g_khi[NROWS * HD];
__device__ __half g_vhi[NROWS * HD];

// ---- packed fp32x2 helpers (FFMA2, full fp32) -----------------------------
__device__ __forceinline__ u64 pack2(float x) {
    u64 r; asm("mov.b64 %0, {%1, %1};" : "=l"(r) : "f"(x)); return r;
}
__device__ __forceinline__ u64 pack2f(float lo, float hi) {
    u64 r; asm("mov.b64 %0, {%1, %2};" : "=l"(r) : "f"(lo), "f"(hi)); return r;
}
__device__ __forceinline__ float2 unpk(u64 v) {
    float2 f; asm("mov.b64 {%0, %1}, %2;" : "=f"(f.x), "=f"(f.y) : "l"(v)); return f;
}
__device__ __forceinline__ void fma2(u64& d, u64 a, u64 b) {
    asm("fma.rn.f32x2 %0, %1, %2, %0;" : "+l"(d) : "l"(a), "l"(b));
}

__device__ __forceinline__ uint32_t smem_to_u32(const void* p) {
    uint32_t a;
    asm("{ .reg .u64 t; cvta.to.shared.u64 t, %1; cvt.u32.u64 %0, t; }"
        : "=r"(a) : "l"(p));
    return a;
}

// XOR swizzle for 128B rows: byte_off ^ ((byte_off>>3)&0x70)
#define SMEM_SWZ(off) ((uint32_t)(off) ^ (((uint32_t)(off) >> 3) & 0x70))

// ---- cp.async (LDGSTS, sm_80+ base ISA) -----------------------------------
#define CP_ASYNC16(saddr, gptr) \
    asm volatile("cp.async.cg.shared.global [%0], [%1], 16;" \
        :: "r"((uint32_t)(saddr)), "l"(gptr) : "memory")
#define CP_COMMIT() asm volatile("cp.async.commit_group;" ::: "memory")
#define CP_WAIT(N)  asm volatile("cp.async.wait_group %0;" :: "n"(N) : "memory")

// ldmatrix x4 (non-transposed, b16)
#define LDSM_X4(r, addr) \
    asm volatile("ldmatrix.sync.aligned.m8n8.x4.shared.b16 {%0,%1,%2,%3}, [%4];" \
        : "=r"((r)[0]), "=r"((r)[1]), "=r"((r)[2]), "=r"((r)[3]) : "r"(addr))

// mma m16n8k16 fp16 in, fp32 accum; C==D accumulate
__device__ __forceinline__ void mma_f16(float c[4], const uint32_t a[4],
                                        uint32_t b0, uint32_t b1) {
    asm volatile(
        "mma.sync.aligned.m16n8k16.row.col.f32.f16.f16.f32 "
        "{%0,%1,%2,%3}, {%4,%5,%6,%7}, {%8,%9}, {%0,%1,%2,%3};"
        : "+f"(c[0]), "+f"(c[1]), "+f"(c[2]), "+f"(c[3])
        : "r"(a[0]), "r"(a[1]), "r"(a[2]), "r"(a[3]), "r"(b0), "r"(b1));
}

__device__ __forceinline__ uint32_t hpack(__half lo, __half hi) {
    __half2 t; t.x = lo; t.y = hi;
    return *(uint32_t*)&t;
}

// async {K,V} tile pair -> ONE commit group.
// K: 64 keys x 64 d contiguous rows (128B). V: 64 d-rows x 64 keys, [d][s] gmem.
__device__ __forceinline__ void cp_tile_KV(uint32_t dstK, uint32_t dstV,
                                           const uint4* kh, const __half* vh,
                                           int tid) {
#pragma unroll
    for (int c = tid; c < 512; c += 128) {
        const uint32_t sw = SMEM_SWZ(c * 16);
        CP_ASYNC16(dstK + sw, kh + c);
        const int row = c >> 3, cb = c & 7;
        CP_ASYNC16(dstV + sw, (const uint4*)(vh + (size_t)row * SEQ) + cb);
    }
    CP_COMMIT();
}

// ---------------------------------------------------------------------------
// Fused projections (fp32 FFMA2 compute, single-fp16 outputs).
// grid (512, 3): y = q/k/v. 128 rows x 64 outputs per block, 256 threads.
// q: scaled by 1/8 (softmax scale folded). v: stored transposed [bh][d][s].
// ---------------------------------------------------------------------------
__global__ __launch_bounds__(256) void proj_kernel(
    const float* __restrict__ Xq, const float* __restrict__ Xk,
    const float* __restrict__ Xv,
    const float* __restrict__ Wq, const float* __restrict__ bq,
    const float* __restrict__ Wk, const float* __restrict__ bk,
    const float* __restrict__ Wv, const float* __restrict__ bv)
{
    const int which = blockIdx.y;
    const float* __restrict__ X    = (which == 0) ? Xq : (which == 1) ? Xk : Xv;
    const float* __restrict__ W    = (which == 0) ? Wq : (which == 1) ? Wk : Wv;
    const float* __restrict__ bias = (which == 0) ? bq : (which == 1) ? bk : bv;

    __shared__ __align__(16) float Xs[128 * 64];
    __shared__ __align__(16) float Ws[64 * 64];   // transposed Wt[d][e]

    const int tid = threadIdx.x;
    const size_t rowBase = (size_t)blockIdx.x * 128;

    {
        const float4* xs = (const float4*)(X + rowBase * HD);
        float4* Xd = (float4*)Xs;
#pragma unroll
        for (int i = 0; i < 8; i++) Xd[tid + i * 256] = xs[tid + i * 256];
    }
#pragma unroll
    for (int i = 0; i < 4; i++) {
        const int idx = tid + i * 256;
        const int e  = idx & 63;
        const int d4 = idx >> 6;
        const float4 w = *(const float4*)&W[e * 64 + d4 * 4];
        Ws[(d4 * 4 + 0) * 64 + e] = w.x;
        Ws[(d4 * 4 + 1) * 64 + e] = w.y;
        Ws[(d4 * 4 + 2) * 64 + e] = w.z;
        Ws[(d4 * 4 + 3) * 64 + e] = w.w;
    }
    __syncthreads();

    const int tr = tid >> 4;
    const int tc = tid & 15;

    u64 acc[8][2];
#pragma unroll
    for (int i = 0; i < 8; i++) { acc[i][0] = 0ull; acc[i][1] = 0ull; }

#pragma unroll 4
    for (int k = 0; k < 64; k += 4) {
        u64 b[4][2];
#pragma unroll
        for (int kk = 0; kk < 4; kk++) {
            const float4 bb = *(const float4*)&Ws[(k + kk) * 64 + tc * 4];
            b[kk][0] = pack2f(bb.x, bb.y);
            b[kk][1] = pack2f(bb.z, bb.w);
        }
#pragma unroll
        for (int i = 0; i < 8; i++) {
            const float4 a = *(const float4*)&Xs[(tr * 8 + i) * 64 + k];
            u64 ap;
            ap = pack2(a.x); fma2(acc[i][0], ap, b[0][0]); fma2(acc[i][1], ap, b[0][1]);
            ap = pack2(a.y); fma2(acc[i][0], ap, b[1][0]); fma2(acc[i][1], ap, b[1][1]);
            ap = pack2(a.z); fma2(acc[i][0], ap, b[2][0]); fma2(acc[i][1], ap, b[2][1]);
            ap = pack2(a.w); fma2(acc[i][0], ap, b[3][0]); fma2(acc[i][1], ap, b[3][1]);
        }
    }

    const float4 bv4 = *(const float4*)&bias[tc * 4];
    float r[8][4];
#pragma unroll
    for (int i = 0; i < 8; i++) {
        const float2 c01 = unpk(acc[i][0]);
        const float2 c23 = unpk(acc[i][1]);
        r[i][0] = fmaxf(c01.x + bv4.x, 0.0f);
        r[i][1] = fmaxf(c01.y + bv4.y, 0.0f);
        r[i][2] = fmaxf(c23.x + bv4.z, 0.0f);
        r[i][3] = fmaxf(c23.y + bv4.w, 0.0f);
    }
    if (which == 0) {   // fold 1/sqrt(64) into q
#pragma unroll
        for (int i = 0; i < 8; i++)
#pragma unroll
            for (int j = 0; j < 4; j++) r[i][j] *= 0.125f;
    }

    if (which == 2) {
        // V transposed, single fp16: g_vhi[(bh*64 + d)*1024 + s]
        const int bh = (int)(rowBase >> 10);
        const int s0 = (int)(rowBase & 1023);
#pragma unroll
        for (int j = 0; j < 4; j++) {
            __half h8[8];
#pragma unroll
            for (int i = 0; i < 8; i++) h8[i] = __float2half_rn(r[i][j]);
            const size_t off = ((size_t)bh * 64 + tc * 4 + j) * 1024 + s0 + tr * 8;
            *(uint4*)&g_vhi[off] = *(uint4*)h8;
        }
    } else {
        // Q / K single fp16
        __half* Y = (which == 0) ? g_qhi : g_khi;
#pragma unroll
        for (int i = 0; i < 8; i++) {
            __half h4[4];
#pragma unroll
            for (int j = 0; j < 4; j++) h4[j] = __float2half_rn(r[i][j]);
            const size_t off = (rowBase + tr * 8 + i) * HD + tc * 4;
            *(uint2*)&Y[off] = *(uint2*)h4;
        }
    }
}

// ---------------------------------------------------------------------------
// mma.sync single-fp16 flash attention, double-buffered cp.async pipeline.
// QK AND PV single-term fp16: per-operand quantization (~2^-11) enters the
// softmax common-mode and cancels — measured +0.5e-6 rel_err when the
// analogous K-side term was dropped (R13). fp32 accum everywhere.
// One CTA = (bh, 64-query tile). 4 warps x 16 q-rows. Grid (16, 64).
//
// SMEM (32KB static; XOR-swizzled 128B rows):
//   [    0: 8192) Khi buf0   [ 8192:16384) Khi buf1 (Q staging)
//   [16384:24576) Vhi buf0   [24576:32768) Vhi buf1
//   As (64x65 f32 epilogue, 16.6KB) overlays [0:16640).
//
// Pipeline (1 cp.async group per {K,V} tile pair):
//   prologue: G0={K0,V0} ; stage Q -> Kb1 ; sync ; extract Q ; sync ;
//             G1={K1,V1}
//   iter kt:  wait_group(kt<15?1:0) -> G_kt landed ; sync ; QK ; exp ; PV ;
//             sync ; if kt<14: G_{kt+2} -> buf[kt&1]
//
// Fragment layouts (PTX mma m16n8k16 row.col), g = lane>>2, q = lane&3:
//   A: a0:(r=g,k=2q+{0,1}) a1:(r=g+8,...) a2:(r=g,k=2q+{8,9}) a3:(r=g+8,...)
//   B: b0:(k=2q+{0,1},n=g) b1:(k=2q+{8,9},n=g)
//   C: c0,c1:(r=g,n=2q,2q+1) c2,c3:(r=g+8,same)
// ---------------------------------------------------------------------------
__global__ __launch_bounds__(128) void attn_kernel(
    const float* __restrict__ queries_in, float* __restrict__ out)
{
    __shared__ __align__(128) char tiles[32768];

    const int tid  = threadIdx.x;
    const int lane = tid & 31;
    const int w    = tid >> 5;
    const int bh = blockIdx.y;
    const int qbase = blockIdx.x * 64;
    const size_t base = (size_t)bh * (SEQ * HD);
    const size_t vbase = (size_t)bh * (HD * SEQ);

    const uint32_t t32 = smem_to_u32(tiles);
    float* As = (float*)tiles;              // epilogue buffer overlays [0:16640)

    // ldmatrix lane->address decomposition
    const int rowA = (lane & 7) + ((lane & 8)  ? 8 : 0);
    const int colA = (lane & 16) ? 16 : 0;
    const int rowB = (lane & 7) + ((lane & 16) ? 8 : 0);
    const int colB = (lane & 8)  ? 16 : 0;

    // ---- G0 = {K0, V0} into buf0 ----
    cp_tile_KV(t32, t32 + 16384,
               (const uint4*)(g_khi + base), g_vhi + vbase, tid);

    // ---- stage Q -> K buf1 (regular stores, swizzled) ----
    {
        const uint4* qh = (const uint4*)(g_qhi + base + (size_t)qbase * HD);
#pragma unroll
        for (int c = tid; c < 512; c += 128) {
            const uint32_t sw = SMEM_SWZ(c * 16);
            *(uint4*)(tiles + 8192 + sw) = qh[c];
        }
    }
    __syncthreads();

    // ---- Q fragments (persist in registers) ----
    uint32_t qh[4][4];
#pragma unroll
    for (int kt2 = 0; kt2 < 4; kt2++) {
        const uint32_t off = SMEM_SWZ((w * 16 + rowA) * 128 + kt2 * 32 + colA);
        LDSM_X4(qh[kt2], t32 + 8192 + off);
    }
    __syncthreads();   // Q reads done -> buf1 free

    // ---- G1 = {K1, V1} into buf1 ----
    cp_tile_KV(t32 + 8192, t32 + 24576,
               (const uint4*)(g_khi + base + 64 * HD), g_vhi + vbase + 64, tid);

    float oa[8][4];
#pragma unroll
    for (int i = 0; i < 8; i++)
#pragma unroll
        for (int j = 0; j < 4; j++) oa[i][j] = 0.0f;
    float lsum0 = 0.0f, lsum1 = 0.0f;

    for (int kt = 0; kt < 16; kt++) {
        const uint32_t kbuf = t32 + ((kt & 1) ? 8192u : 0u);
        const uint32_t vbuf = t32 + 16384 + ((kt & 1) ? 8192u : 0u);

        if (kt < 15) { CP_WAIT(1); } else { CP_WAIT(0); }   // G_kt landed
        __syncthreads();

        // ---- S = Q * K ----
        float sa[8][4];
#pragma unroll
        for (int i = 0; i < 8; i++)
#pragma unroll
            for (int j = 0; j < 4; j++) sa[i][j] = 0.0f;

#pragma unroll
        for (int np = 0; np < 4; np++) {
#pragma unroll
            for (int kt2 = 0; kt2 < 4; kt2++) {
                const uint32_t off = SMEM_SWZ((np * 16 + rowB) * 128 + kt2 * 32 + colB);
                uint32_t bkh[4];
                LDSM_X4(bkh, kbuf + off);
                mma_f16(sa[2 * np],     qh[kt2], bkh[0], bkh[1]);
                mma_f16(sa[2 * np + 1], qh[kt2], bkh[2], bkh[3]);
            }
        }

        // ---- P = exp(S) -> fp16; lsum over QUANTIZED values ----
        uint32_t phi[4][4];
#pragma unroll
        for (int nt = 0; nt < 8; nt++) {
            const __half h0 = __float2half_rn(__expf(sa[nt][0]));
            const __half h1 = __float2half_rn(__expf(sa[nt][1]));
            const __half h2 = __float2half_rn(__expf(sa[nt][2]));
            const __half h3 = __float2half_rn(__expf(sa[nt][3]));
            lsum0 += __half2float(h0) + __half2float(h1);
            lsum1 += __half2float(h2) + __half2float(h3);
            const int kt2 = nt >> 1, sl = (nt & 1) * 2;
            phi[kt2][sl]     = hpack(h0, h1);
            phi[kt2][sl + 1] = hpack(h2, h3);
        }

        // ---- O += P * V ----
#pragma unroll
        for (int np = 0; np < 4; np++) {
#pragma unroll
            for (int kt2 = 0; kt2 < 4; kt2++) {
                const uint32_t off = SMEM_SWZ((np * 16 + rowB) * 128 + kt2 * 32 + colB);
                uint32_t bvh[4];
                LDSM_X4(bvh, vbuf + off);
                mma_f16(oa[2 * np],     phi[kt2], bvh[0], bvh[1]);
                mma_f16(oa[2 * np + 1], phi[kt2], bvh[2], bvh[3]);
            }
        }

        __syncthreads();   // all reads of buf[kt&1] done
        if (kt < 14) {     // G_{kt+2} into buf[kt&1]
            cp_tile_KV(kbuf, vbuf,
                       (const uint4*)(g_khi + base + (size_t)(kt + 2) * 64 * HD),
                       g_vhi + vbase + (kt + 2) * 64, tid);
        }
    }

    // ---- finalize row sums (linear -> single quad reduction) ----
    lsum0 += __shfl_xor_sync(0xffffffffu, lsum0, 1);
    lsum0 += __shfl_xor_sync(0xffffffffu, lsum0, 2);
    lsum1 += __shfl_xor_sync(0xffffffffu, lsum1, 1);
    lsum1 += __shfl_xor_sync(0xffffffffu, lsum1, 2);
    const float inv0 = 1.0f / lsum0;
    const float inv1 = 1.0f / lsum1;

    // stage normalized O into As[s_local][d] (stride 65); the loop-end
    // __syncthreads() of kt=15 ordered all tile reads before these writes.
    {
        const int r0 = w * 16 + (lane >> 2);
        const int r1 = r0 + 8;
#pragma unroll
        for (int nt = 0; nt < 8; nt++) {
            const int d0 = nt * 8 + (lane & 3) * 2;
            As[r0 * 65 + d0]     = oa[nt][0] * inv0;
            As[r0 * 65 + d0 + 1] = oa[nt][1] * inv0;
            As[r1 * 65 + d0]     = oa[nt][2] * inv1;
            As[r1 * 65 + d0 + 1] = oa[nt][3] * inv1;
        }
    }
    __syncthreads();

    // out[bh][lin] = a[s = lin&1023][d = lin>>10] + queries_in[bh][lin]
    const float* qin = queries_in + base;
    float* op = out + base;
#pragma unroll
    for (int t = 0; t < 32; t++) {
        const int idx = tid + t * 128;       // 0..4095
        const int d  = idx >> 6;
        const int sl = idx & 63;
        const int lin = d * 1024 + qbase + sl;
        op[lin] = As[sl * 65 + d] + qin[lin];
    }
}

// ---------------------------------------------------------------------------
// Launch: inputs in metadata order:
//  0 queries, 1 keys, 2 values, 3 Wq_w, 4 Wq_b, 5 Wk_w, 6 Wk_b, 7 Wv_w, 8 Wv_b
// ---------------------------------------------------------------------------
extern "C" void kernel_launch(void* const* d_in, const int* in_sizes, int n_in,
                              void* d_out, int out_size)
{
    const float* q  = (const float*)d_in[0];
    const float* k  = (const float*)d_in[1];
    const float* v  = (const float*)d_in[2];
    const float* Wq = (const float*)d_in[3];
    const float* bq = (const float*)d_in[4];
    const float* Wk = (const float*)d_in[5];
    const float* bk = (const float*)d_in[6];
    const float* Wv = (const float*)d_in[7];
    const float* bv = (const float*)d_in[8];
    float* out = (float*)d_out;

    proj_kernel<<<dim3(512, 3), 256>>>(q, k, v, Wq, bq, Wk, bk, Wv, bv);
    attn_kernel<<<dim3(16, 64), 128>>>(q, out);
}